// round 2
// baseline (speedup 1.0000x reference)
#include <cuda_runtime.h>
#include <cstdint>

// ---------------------------------------------------------------------------
// Problem constants
//   c3   : [16, 512, 64, 64] f32
//   c4   : [16,1024, 32, 32] f32
//   boxes: [16, 10, 4] f32
//   w    : [512, 1536] f32 (1x1 conv over concat(c3, up2x(c4)))
//   out  : boxes (640 f32) ++ obj_blob [16,10,512,5,5] (2,048,000 f32)
// ---------------------------------------------------------------------------
#define NB   16
#define CF   1536   // fused channels
#define OC   512    // output channels
#define HW   4096   // 64*64
#define KD   1536

// Scratch (device globals — allocation-free per harness rules)
__device__ float g_fused[100663296];   // 16*1536*4096  (384 MiB)
__device__ float g_attr [33554432];    // 16* 512*4096  (128 MiB)

// ---------------------------------------------------------------------------
// f32x2 packed-FMA helpers (sm_103a)
// ---------------------------------------------------------------------------
__device__ __forceinline__ unsigned long long splat2(float x) {
    unsigned long long r;
    asm("mov.b64 %0, {%1, %1};" : "=l"(r) : "f"(x));
    return r;
}
__device__ __forceinline__ void fma2(unsigned long long& d,
                                     unsigned long long a,
                                     unsigned long long b) {
    asm("fma.rn.f32x2 %0, %1, %2, %0;" : "+l"(d) : "l"(a), "l"(b));
}
__device__ __forceinline__ float2 unpack2(unsigned long long v) {
    float2 f;
    asm("mov.b64 {%0, %1}, %2;" : "=f"(f.x), "=f"(f.y) : "l"(v));
    return f;
}

// ---------------------------------------------------------------------------
// Kernel 1: build fused = concat(c3, bilinear2x(c4))   [b][c][h*64+w]
// half-pixel bilinear, edge clamp (matches jax.image.resize 'bilinear' 2x)
// ---------------------------------------------------------------------------
__global__ void fuse_kernel(const float* __restrict__ c3,
                            const float* __restrict__ c4) {
    long i4 = (long)blockIdx.x * blockDim.x + threadIdx.x;
    const long total4 = 100663296L / 4;
    if (i4 >= total4) return;
    long idx = i4 * 4;
    int hw = (int)(idx & 4095);
    int t  = (int)(idx >> 12);
    int c  = t % CF;
    int b  = t / CF;
    float4 out;
    if (c < 512) {
        out = *(const float4*)(c3 + (((long)(b * 512 + c)) << 12) + hw);
    } else {
        int cc = c - 512;
        const float* src = c4 + ((long)(b * 1024 + cc)) * 1024;
        int h = hw >> 6, w0 = hw & 63;
        float syf = h * 0.5f - 0.25f;
        float y0f = floorf(syf);
        float fy  = syf - y0f;
        int iy0 = max(0, min(31, (int)y0f));
        int iy1 = max(0, min(31, (int)y0f + 1));
        const float* r0 = src + iy0 * 32;
        const float* r1 = src + iy1 * 32;
        float v[4];
#pragma unroll
        for (int j = 0; j < 4; j++) {
            int w = w0 + j;
            float sxf = w * 0.5f - 0.25f;
            float x0f = floorf(sxf);
            float fx  = sxf - x0f;
            int ix0 = max(0, min(31, (int)x0f));
            int ix1 = max(0, min(31, (int)x0f + 1));
            float a  = r0[ix0] * (1.f - fx) + r0[ix1] * fx;
            float bb = r1[ix0] * (1.f - fx) + r1[ix1] * fx;
            v[j] = a * (1.f - fy) + bb * fy;
        }
        out = make_float4(v[0], v[1], v[2], v[3]);
    }
    *(float4*)(g_fused + idx) = out;
}

// ---------------------------------------------------------------------------
// Kernel 2: GEMM  attr[b][o][hw] = relu(bn(sum_c W[o][c]*fused[b][c][hw]))
// 128x128 tile, BK=16, double-buffered SMEM, f32x2 packed FMA core.
// ---------------------------------------------------------------------------
__global__ __launch_bounds__(256) void gemm_kernel(
    const float* __restrict__ Wc,   const float* __restrict__ bconv,
    const float* __restrict__ gamma,const float* __restrict__ beta,
    const float* __restrict__ mean, const float* __restrict__ var) {
    __shared__ float As[2][16][128];   // As[k][m]  (W transposed)
    __shared__ float Bs[2][16][128];   // Bs[k][n]

    const int tid = threadIdx.x;
    const int n0  = blockIdx.x * 128;
    const int m0  = blockIdx.y * 128;
    const int b   = n0 >> 12;
    const int hw0 = n0 & 4095;
    const float* Xb = g_fused + ((long)b * CF) * HW + hw0;

    const int tx = tid & 15, ty = tid >> 4;

    // A loader: 128 rows x 16 k, 2 float4/thread (row = lin/4, quad = lin%4)
    const int aRow0 = tid >> 2;
    const int aRow1 = aRow0 + 64;          // (tid+256)/4
    const int aQuad = tid & 3;
    // B loader: 16 k-rows x 128 n, 2 float4/thread (kr = lin/32, nq = lin%32)
    const int bKr0 = tid >> 5;
    const int bKr1 = bKr0 + 8;
    const int bNq  = tid & 31;

    float4 aReg0, aReg1, bReg0, bReg1;

    // ---- preload tile 0 ----
    aReg0 = *(const float4*)(Wc + (long)(m0 + aRow0) * KD + aQuad * 4);
    aReg1 = *(const float4*)(Wc + (long)(m0 + aRow1) * KD + aQuad * 4);
    bReg0 = *(const float4*)(Xb + (long)bKr0 * HW + bNq * 4);
    bReg1 = *(const float4*)(Xb + (long)bKr1 * HW + bNq * 4);

    As[0][aQuad * 4 + 0][aRow0] = aReg0.x;
    As[0][aQuad * 4 + 1][aRow0] = aReg0.y;
    As[0][aQuad * 4 + 2][aRow0] = aReg0.z;
    As[0][aQuad * 4 + 3][aRow0] = aReg0.w;
    As[0][aQuad * 4 + 0][aRow1] = aReg1.x;
    As[0][aQuad * 4 + 1][aRow1] = aReg1.y;
    As[0][aQuad * 4 + 2][aRow1] = aReg1.z;
    As[0][aQuad * 4 + 3][aRow1] = aReg1.w;
    *(float4*)&Bs[0][bKr0][bNq * 4] = bReg0;
    *(float4*)&Bs[0][bKr1][bNq * 4] = bReg1;
    __syncthreads();

    unsigned long long acc[8][4];
#pragma unroll
    for (int i = 0; i < 8; i++)
#pragma unroll
        for (int j = 0; j < 4; j++) acc[i][j] = 0ull;

    const int NT = KD / 16;   // 96
    for (int t = 0; t < NT; ++t) {
        const int cur = t & 1;
        if (t < NT - 1) {
            const int k0 = (t + 1) * 16;
            aReg0 = *(const float4*)(Wc + (long)(m0 + aRow0) * KD + k0 + aQuad * 4);
            aReg1 = *(const float4*)(Wc + (long)(m0 + aRow1) * KD + k0 + aQuad * 4);
            bReg0 = *(const float4*)(Xb + (long)(k0 + bKr0) * HW + bNq * 4);
            bReg1 = *(const float4*)(Xb + (long)(k0 + bKr1) * HW + bNq * 4);
        }
#pragma unroll
        for (int kk = 0; kk < 16; ++kk) {
            float4 a0 = *(const float4*)&As[cur][kk][ty * 4];
            float4 a1 = *(const float4*)&As[cur][kk][64 + ty * 4];
            ulonglong2 bv0 = *(const ulonglong2*)&Bs[cur][kk][tx * 4];
            ulonglong2 bv1 = *(const ulonglong2*)&Bs[cur][kk][64 + tx * 4];
            const unsigned long long bb0 = bv0.x, bb1 = bv0.y;
            const unsigned long long bb2 = bv1.x, bb3 = bv1.y;
            const float av[8] = {a0.x, a0.y, a0.z, a0.w, a1.x, a1.y, a1.z, a1.w};
#pragma unroll
            for (int i = 0; i < 8; ++i) {
                unsigned long long s = splat2(av[i]);
                fma2(acc[i][0], s, bb0);
                fma2(acc[i][1], s, bb1);
                fma2(acc[i][2], s, bb2);
                fma2(acc[i][3], s, bb3);
            }
        }
        if (t < NT - 1) {
            __syncthreads();
            const int buf = cur ^ 1;
            As[buf][aQuad * 4 + 0][aRow0] = aReg0.x;
            As[buf][aQuad * 4 + 1][aRow0] = aReg0.y;
            As[buf][aQuad * 4 + 2][aRow0] = aReg0.z;
            As[buf][aQuad * 4 + 3][aRow0] = aReg0.w;
            As[buf][aQuad * 4 + 0][aRow1] = aReg1.x;
            As[buf][aQuad * 4 + 1][aRow1] = aReg1.y;
            As[buf][aQuad * 4 + 2][aRow1] = aReg1.z;
            As[buf][aQuad * 4 + 3][aRow1] = aReg1.w;
            *(float4*)&Bs[buf][bKr0][bNq * 4] = bReg0;
            *(float4*)&Bs[buf][bKr1][bNq * 4] = bReg1;
            __syncthreads();
        }
    }

    // ---- epilogue: +bias, eval-BN, relu, store NCHW ----
    float* outp = g_attr + ((long)b * OC) * HW + hw0;
#pragma unroll
    for (int i = 0; i < 8; i++) {
        const int m = (i < 4) ? (ty * 4 + i) : (64 + ty * 4 + (i - 4));
        const int o = m0 + m;
        const float inv  = gamma[o] * rsqrtf(var[o] + 1e-5f);
        const float bias = (bconv[o] - mean[o]) * inv + beta[o];
        float2 p0 = unpack2(acc[i][0]);
        float2 p1 = unpack2(acc[i][1]);
        float2 p2 = unpack2(acc[i][2]);
        float2 p3 = unpack2(acc[i][3]);
        float4 v0 = make_float4(fmaxf(p0.x * inv + bias, 0.f),
                                fmaxf(p0.y * inv + bias, 0.f),
                                fmaxf(p1.x * inv + bias, 0.f),
                                fmaxf(p1.y * inv + bias, 0.f));
        float4 v1 = make_float4(fmaxf(p2.x * inv + bias, 0.f),
                                fmaxf(p2.y * inv + bias, 0.f),
                                fmaxf(p3.x * inv + bias, 0.f),
                                fmaxf(p3.y * inv + bias, 0.f));
        *(float4*)(outp + (long)o * HW + tx * 4)      = v0;
        *(float4*)(outp + (long)o * HW + 64 + tx * 4) = v1;
    }
}

// ---------------------------------------------------------------------------
// Kernel 3: ROI adaptive-avg-pool 5x5.
// grid (160, 4): block = (box, 128-channel slice); warp = channel; lanes = cols.
// Deterministic butterfly reductions (no atomics).
// ---------------------------------------------------------------------------
__global__ void pool_kernel(const float* __restrict__ boxes,
                            float* __restrict__ obj) {
    const int br = blockIdx.x;          // b*10 + r
    const int b  = br / 10;
    const float* bx = boxes + br * 4;
    const float b0 = bx[0], b1 = bx[1], b2 = bx[2], b3 = bx[3];

    int x1 = min(63, max(0, (int)floorf(b0 * 0.125f)));
    int y1 = min(63, max(0, (int)floorf(b1 * 0.125f)));
    int x2 = min(63, max(0, (int)ceilf (b2 * 0.125f)));
    int y2 = min(63, max(0, (int)ceilf (b3 * 0.125f)));
    if (x2 <= x1) x2 = min(x1 + 1, 64);
    if (y2 <= y1) y2 = min(y1 + 1, 64);
    const int Lx = x2 - x1, Ly = y2 - y1;

    int xs[5], xe[5], ys[5], ye[5];
    float invx[5], invy[5];
#pragma unroll
    for (int k = 0; k < 5; k++) {
        xs[k] = x1 + (k * Lx) / 5;
        xe[k] = x1 + ((k + 1) * Lx + 4) / 5;
        ys[k] = y1 + (k * Ly) / 5;
        ye[k] = y1 + ((k + 1) * Ly + 4) / 5;
        invx[k] = 1.f / (float)(xe[k] - xs[k]);
        invy[k] = 1.f / (float)(ye[k] - ys[k]);
    }

    const int warp = threadIdx.x >> 5, lane = threadIdx.x & 31;
    const int c0 = blockIdx.y * 128;
    const float* base = g_attr + (long)b * OC * HW;

    for (int c = c0 + warp; c < c0 + 128; c += 8) {
        const float* ch = base + (long)c * HW;
        float bins[25];
#pragma unroll
        for (int t = 0; t < 25; t++) bins[t] = 0.f;

        for (int cw = 0; cw < Lx; cw += 32) {
            const int  col = x1 + cw + lane;
            const bool act = (cw + lane) < Lx;
            float colsum[5] = {0.f, 0.f, 0.f, 0.f, 0.f};
            if (act) {
                for (int h = y1; h < y2; h++) {
                    const float v = __ldg(ch + h * 64 + col);
#pragma unroll
                    for (int p = 0; p < 5; p++)
                        if (h >= ys[p] && h < ye[p]) colsum[p] += v * invy[p];
                }
            }
#pragma unroll
            for (int p = 0; p < 5; p++) {
#pragma unroll
                for (int q = 0; q < 5; q++) {
                    const float wq = (act && col >= xs[q] && col < xe[q]) ? invx[q] : 0.f;
                    float v = colsum[p] * wq;
                    v += __shfl_xor_sync(0xffffffffu, v, 16);
                    v += __shfl_xor_sync(0xffffffffu, v, 8);
                    v += __shfl_xor_sync(0xffffffffu, v, 4);
                    v += __shfl_xor_sync(0xffffffffu, v, 2);
                    v += __shfl_xor_sync(0xffffffffu, v, 1);
                    bins[p * 5 + q] += v;
                }
            }
        }
        if (lane < 25) {
            float vout = 0.f;
#pragma unroll
            for (int t = 0; t < 25; t++)
                if (lane == t) vout = bins[t];
            obj[((long)br * OC + c) * 25 + lane] = vout;
        }
    }
}

__global__ void copy_boxes_kernel(const float* __restrict__ boxes,
                                  float* __restrict__ out) {
    int i = blockIdx.x * blockDim.x + threadIdx.x;
    if (i < 640) out[i] = boxes[i];
}

// ---------------------------------------------------------------------------
extern "C" void kernel_launch(void* const* d_in, const int* in_sizes, int n_in,
                              void* d_out, int out_size) {
    const float* c3    = (const float*)d_in[0];
    const float* c4    = (const float*)d_in[1];
    const float* boxes = (const float*)d_in[2];
    const float* w     = (const float*)d_in[3];
    const float* bconv = (const float*)d_in[4];
    const float* gamma = (const float*)d_in[5];
    const float* beta  = (const float*)d_in[6];
    const float* mean  = (const float*)d_in[7];
    const float* var   = (const float*)d_in[8];

    float* out = (float*)d_out;
    float* obj = out;
    if (out_size >= 640 + 16 * 10 * 512 * 25) {   // boxes ++ obj layout
        copy_boxes_kernel<<<3, 256>>>(boxes, out);
        obj = out + 640;
    }

    const long total4 = 100663296L / 4;
    fuse_kernel<<<(int)((total4 + 255) / 256), 256>>>(c3, c4);

    dim3 ggrid(512, 4);   // 512 n-tiles (N=65536/128), 4 m-tiles (M=512/128)
    gemm_kernel<<<ggrid, 256>>>(w, bconv, gamma, beta, mean, var);

    pool_kernel<<<dim3(160, 4), 256>>>(boxes, obj);
}

// round 4
// speedup vs baseline: 2.3325x; 2.3325x over previous
#include <cuda_runtime.h>
#include <cuda_bf16.h>
#include <cstdint>

// ---------------------------------------------------------------------------
//   c3   : [16, 512, 64, 64] f32
//   c4   : [16,1024, 32, 32] f32
//   boxes: [16, 10, 4] f32
//   w    : [512, 1536] f32
//   out  : boxes (640 f32) ++ obj_blob [16,10,512,5,5]
// ---------------------------------------------------------------------------
#define CF   1536
#define OC   512
#define HW   4096
#define KD   1536

// Scratch (device globals — allocation-free)
__device__ __align__(128) __nv_bfloat16 g_whi[OC * KD];          // W hi
__device__ __align__(128) __nv_bfloat16 g_wlo[OC * KD];          // W lo
__device__ __align__(128) __nv_bfloat16 g_bhi[16L * HW * KD];    // fusedT hi [b][hw][k]
__device__ __align__(128) __nv_bfloat16 g_blo[16L * HW * KD];    // fusedT lo
__device__ __align__(128) float         g_attr[16L * OC * HW];   // relu(bn(conv))

// ---------------------------------------------------------------------------
// PTX helpers (baseline ISA only — no 'a'-target features)
// ---------------------------------------------------------------------------
__device__ __forceinline__ uint32_t smem_u32(const void* p) {
    uint32_t a;
    asm("{ .reg .u64 t; cvta.to.shared.u64 t, %1; cvt.u32.u64 %0, t; }" : "=r"(a) : "l"(p));
    return a;
}
__device__ __forceinline__ void cp16(uint32_t dst, const void* src) {
    asm volatile("cp.async.cg.shared.global [%0], [%1], 16;" :: "r"(dst), "l"(src));
}
#define CP_COMMIT() asm volatile("cp.async.commit_group;" ::: "memory")
#define CP_WAIT0()  asm volatile("cp.async.wait_group 0;" ::: "memory")
#define CP_WAIT1()  asm volatile("cp.async.wait_group 1;" ::: "memory")

#define LDSM4(r, a) \
    asm volatile("ldmatrix.sync.aligned.m8n8.x4.shared.b16 {%0,%1,%2,%3}, [%4];" \
                 : "=r"((r)[0]), "=r"((r)[1]), "=r"((r)[2]), "=r"((r)[3]) : "r"(a))

__device__ __forceinline__ void mma_bf16(float* c, const uint32_t* a,
                                         uint32_t b0, uint32_t b1) {
    asm volatile(
        "mma.sync.aligned.m16n8k16.row.col.f32.bf16.bf16.f32 "
        "{%0,%1,%2,%3}, {%4,%5,%6,%7}, {%8,%9}, {%0,%1,%2,%3};"
        : "+f"(c[0]), "+f"(c[1]), "+f"(c[2]), "+f"(c[3])
        : "r"(a[0]), "r"(a[1]), "r"(a[2]), "r"(a[3]), "r"(b0), "r"(b1));
}

// XOR swizzle: matrix stored as 128 rows x 4 chunks of 16B (64B rows).
// Conflict-free for 16B cp.async stores AND all ldmatrix 8-row phases.
__device__ __forceinline__ uint32_t swz(int row, int c) {
    return (uint32_t)(row * 64 + ((c ^ (row & 3) ^ ((row >> 2) & 1)) << 4));
}

// ---------------------------------------------------------------------------
// Kernel 0: split W into bf16 hi/lo
// ---------------------------------------------------------------------------
__global__ void wsplit_kernel(const float* __restrict__ w) {
    int i = blockIdx.x * 256 + threadIdx.x;
    if (i < OC * KD) {
        float v = w[i];
        __nv_bfloat16 h = __float2bfloat16(v);
        g_whi[i] = h;
        g_wlo[i] = __float2bfloat16(v - __bfloat162float(h));
    }
}

// ---------------------------------------------------------------------------
// Kernel 1: fused = concat(c3, bilinear2x(c4)) -> TRANSPOSED bf16 hi/lo
//   layout [b][hw][k], k contiguous.  grid (16 b, 24 ctile, 64 h)
// ---------------------------------------------------------------------------
__global__ __launch_bounds__(256) void fuse_kernel(const float* __restrict__ c3,
                                                   const float* __restrict__ c4) {
    __shared__ __nv_bfloat16 s_hi[64][66];
    __shared__ __nv_bfloat16 s_lo[64][66];
    const int b  = blockIdx.x;
    const int ct = blockIdx.y;
    const int h  = blockIdx.z;
    const int tid = threadIdx.x;
    const int c0 = ct * 64;

    const float syf = h * 0.5f - 0.25f;
    const float y0f = floorf(syf);
    const float fy  = syf - y0f;
    const int  iy0 = max(0, min(31, (int)y0f));
    const int  iy1 = max(0, min(31, (int)y0f + 1));

    for (int idx = tid; idx < 4096; idx += 256) {
        const int w = idx & 63;
        const int c = idx >> 6;
        const int cg = c0 + c;
        float v;
        if (cg < 512) {
            v = c3[(((long)(b * 512 + cg)) << 12) + h * 64 + w];
        } else {
            const int cc = cg - 512;
            const float* src = c4 + ((long)(b * 1024 + cc)) * 1024;
            const float sxf = w * 0.5f - 0.25f;
            const float x0f = floorf(sxf);
            const float fx  = sxf - x0f;
            const int ix0 = max(0, min(31, (int)x0f));
            const int ix1 = max(0, min(31, (int)x0f + 1));
            const float* r0 = src + iy0 * 32;
            const float* r1 = src + iy1 * 32;
            const float a  = r0[ix0] * (1.f - fx) + r0[ix1] * fx;
            const float bb = r1[ix0] * (1.f - fx) + r1[ix1] * fx;
            v = a * (1.f - fy) + bb * fy;
        }
        const __nv_bfloat16 hi = __float2bfloat16(v);
        s_hi[w][c] = hi;
        s_lo[w][c] = __float2bfloat16(v - __bfloat162float(hi));
    }
    __syncthreads();

    uint32_t* dh = (uint32_t*)g_bhi;
    uint32_t* dl = (uint32_t*)g_blo;
    for (int idx = tid; idx < 2048; idx += 256) {
        const int cp = idx & 31;
        const int w  = idx >> 5;
        const int cc = cp * 2;
        uint32_t vh = (uint32_t)*(const uint16_t*)&s_hi[w][cc] |
                      ((uint32_t)*(const uint16_t*)&s_hi[w][cc + 1] << 16);
        uint32_t vl = (uint32_t)*(const uint16_t*)&s_lo[w][cc] |
                      ((uint32_t)*(const uint16_t*)&s_lo[w][cc + 1] << 16);
        const long row = (long)b * 4096 + h * 64 + w;
        dh[row * 768 + ct * 32 + cp] = vh;
        dl[row * 768 + ct * 32 + cp] = vl;
    }
}

// ---------------------------------------------------------------------------
// Kernel 2: mma.sync bf16 GEMM  attr = relu(bn(W @ fusedT^T))
//   CTA 128x128, BK=32 double-buffered cp.async, 8 warps (2m x 4n),
//   warp tile 64x32, 3-term bf16-split accumulation in f32.
// ---------------------------------------------------------------------------
#define STG_BYTES 32768           // 4 matrices x 8KB per stage
#define MAT_AH 0
#define MAT_AL 8192
#define MAT_BH 16384
#define MAT_BL 24576
#define BN_OFF (2 * STG_BYTES)    // 65536
#define GEMM_SMEM (BN_OFF + 1024)

__global__ __launch_bounds__(256, 2)
void gemm_kernel(const float* __restrict__ bconv, const float* __restrict__ gamma,
                 const float* __restrict__ beta,  const float* __restrict__ mean,
                 const float* __restrict__ var) {
    extern __shared__ char smem[];
    const uint32_t sb = smem_u32(smem);
    const int tid  = threadIdx.x;
    const int wid  = tid >> 5, lane = tid & 31;
    const int wm   = wid >> 2;            // 0..1  (m quadrant, 64 rows)
    const int wn   = wid & 3;             // 0..3  (n quadrant, 32 cols)
    const int m0   = blockIdx.x * 128;
    const int ny   = blockIdx.y;
    const int bI   = ny >> 5;
    const int hw0  = (ny & 31) * 128;

    // BN constants for this m-tile
    float* s_inv  = (float*)(smem + BN_OFF);
    float* s_bias = s_inv + 128;
    if (tid < 128) {
        const int o = m0 + tid;
        const float iv = gamma[o] * rsqrtf(var[o] + 1e-5f);
        s_inv[tid]  = iv;
        s_bias[tid] = (bconv[o] - mean[o]) * iv + beta[o];
    }

    const uint4* Wh = (const uint4*)g_whi;
    const uint4* Wl = (const uint4*)g_wlo;
    const uint4* Fh = (const uint4*)g_bhi;
    const uint4* Fl = (const uint4*)g_blo;
    const long  brow = (long)bI * 4096 + hw0;     // base n-row in fusedT

    // per-thread load slots: 2 per matrix (rows tid>>2 and 64+tid>>2)
    const int lr0 = tid >> 2, lc = tid & 3;
    const uint32_t so0 = swz(lr0, lc), so1 = swz(lr0 + 64, lc);

    auto load_stage = [&](int buf, int t) {
        const uint32_t stg = sb + buf * STG_BYTES;
        const int kq = t * 4;                     // uint4 offset in k
        cp16(stg + MAT_AH + so0, Wh + (long)(m0 + lr0) * 192 + kq + lc);
        cp16(stg + MAT_AH + so1, Wh + (long)(m0 + lr0 + 64) * 192 + kq + lc);
        cp16(stg + MAT_AL + so0, Wl + (long)(m0 + lr0) * 192 + kq + lc);
        cp16(stg + MAT_AL + so1, Wl + (long)(m0 + lr0 + 64) * 192 + kq + lc);
        cp16(stg + MAT_BH + so0, Fh + (brow + lr0) * 192 + kq + lc);
        cp16(stg + MAT_BH + so1, Fh + (brow + lr0 + 64) * 192 + kq + lc);
        cp16(stg + MAT_BL + so0, Fl + (brow + lr0) * 192 + kq + lc);
        cp16(stg + MAT_BL + so1, Fl + (brow + lr0 + 64) * 192 + kq + lc);
    };

    float acc[4][4][4];
#pragma unroll
    for (int i = 0; i < 4; i++)
#pragma unroll
        for (int j = 0; j < 4; j++)
#pragma unroll
            for (int k = 0; k < 4; k++) acc[i][j][k] = 0.f;

    // lane components for ldmatrix addressing
    const int r8     = lane & 7;
    const int a_row  = ((lane >> 3) & 1) * 8 + r8;      // + mf*16
    const int a_cHi  = lane >> 4;                       // + 2*kg
    const int b_row  = wn * 32 + ((lane >> 4) & 1) * 8 + r8;   // + j*16
    const int b_cHi  = (lane >> 3) & 1;                 // + 2*kg

    load_stage(0, 0);
    CP_COMMIT();

    for (int t = 0; t < 48; ++t) {
        if (t + 1 < 48) { load_stage((t + 1) & 1, t + 1); CP_COMMIT(); CP_WAIT1(); }
        else            { CP_WAIT0(); }
        __syncthreads();

        const uint32_t stg = sb + (t & 1) * STG_BYTES;
#pragma unroll
        for (int kg = 0; kg < 2; ++kg) {
            // B fragments: 2 x4-ldmatrix per operand -> 4 n8-tiles
            uint32_t bh[8], bl[8];
#pragma unroll
            for (int j = 0; j < 2; ++j) {
                const uint32_t ba = swz(b_row + j * 16, 2 * kg + b_cHi);
                LDSM4(bh + j * 4, stg + MAT_BH + ba);
                LDSM4(bl + j * 4, stg + MAT_BL + ba);
            }
#pragma unroll
            for (int mf = 0; mf < 4; ++mf) {
                uint32_t ah[4], al[4];
                const uint32_t aa = swz(wm * 64 + mf * 16 + a_row, 2 * kg + a_cHi);
                LDSM4(ah, stg + MAT_AH + aa);
                LDSM4(al, stg + MAT_AL + aa);
#pragma unroll
                for (int nf = 0; nf < 4; ++nf) {
                    mma_bf16(acc[mf][nf], ah, bh[nf * 2], bh[nf * 2 + 1]);
                    mma_bf16(acc[mf][nf], ah, bl[nf * 2], bl[nf * 2 + 1]);
                    mma_bf16(acc[mf][nf], al, bh[nf * 2], bh[nf * 2 + 1]);
                }
            }
        }
        __syncthreads();
    }

    // epilogue: BN + relu, direct stores (float2 per fragment row)
    const int g = lane >> 2, tq = lane & 3;
    float* attr = g_attr + ((long)bI * OC + m0) * HW + hw0;
#pragma unroll
    for (int mf = 0; mf < 4; ++mf) {
        const int ml0 = wm * 64 + mf * 16 + g;
        const int ml1 = ml0 + 8;
        const float i0 = s_inv[ml0], z0 = s_bias[ml0];
        const float i1 = s_inv[ml1], z1 = s_bias[ml1];
#pragma unroll
        for (int nf = 0; nf < 4; ++nf) {
            const int n = wn * 32 + nf * 8 + 2 * tq;
            float2 v0 = make_float2(fmaxf(acc[mf][nf][0] * i0 + z0, 0.f),
                                    fmaxf(acc[mf][nf][1] * i0 + z0, 0.f));
            float2 v1 = make_float2(fmaxf(acc[mf][nf][2] * i1 + z1, 0.f),
                                    fmaxf(acc[mf][nf][3] * i1 + z1, 0.f));
            *(float2*)(attr + (long)ml0 * HW + n) = v0;
            *(float2*)(attr + (long)ml1 * HW + n) = v1;
        }
    }
}

// ---------------------------------------------------------------------------
// Kernel 3: ROI adaptive-avg-pool 5x5.  grid (160, 64): warp = (box, channel)
// ---------------------------------------------------------------------------
__global__ __launch_bounds__(256) void pool_kernel(const float* __restrict__ boxes,
                                                   float* __restrict__ obj) {
    const int br = blockIdx.x;
    const int b  = br / 10;
    const float* bx = boxes + br * 4;

    int x1 = min(63, max(0, (int)floorf(bx[0] * 0.125f)));
    int y1 = min(63, max(0, (int)floorf(bx[1] * 0.125f)));
    int x2 = min(63, max(0, (int)ceilf (bx[2] * 0.125f)));
    int y2 = min(63, max(0, (int)ceilf (bx[3] * 0.125f)));
    if (x2 <= x1) x2 = min(x1 + 1, 64);
    if (y2 <= y1) y2 = min(y1 + 1, 64);
    const int Lx = x2 - x1, Ly = y2 - y1;

    int xs[5], xe[5], ys[5], ye[5];
    float invx[5], invy[5];
#pragma unroll
    for (int k = 0; k < 5; k++) {
        xs[k] = x1 + (k * Lx) / 5;
        xe[k] = x1 + ((k + 1) * Lx + 4) / 5;
        ys[k] = y1 + (k * Ly) / 5;
        ye[k] = y1 + ((k + 1) * Ly + 4) / 5;
        invx[k] = 1.f / (float)(xe[k] - xs[k]);
        invy[k] = 1.f / (float)(ye[k] - ys[k]);
    }

    const int warp = threadIdx.x >> 5, lane = threadIdx.x & 31;
    const int c = blockIdx.y * 8 + warp;
    const float* ch = g_attr + ((long)b * OC + c) * HW;

    float bins[25];
#pragma unroll
    for (int t = 0; t < 25; t++) bins[t] = 0.f;

    for (int cw = 0; cw < Lx; cw += 32) {
        const int  col = x1 + cw + lane;
        const bool act = (cw + lane) < Lx;
        float colsum[5] = {0.f, 0.f, 0.f, 0.f, 0.f};
        if (act) {
#pragma unroll 4
            for (int h = y1; h < y2; h++) {
                const float v = __ldg(ch + h * 64 + col);
#pragma unroll
                for (int p = 0; p < 5; p++)
                    if (h >= ys[p] && h < ye[p]) colsum[p] += v * invy[p];
            }
        }
#pragma unroll
        for (int q = 0; q < 5; q++) {
            const float wq = (act && col >= xs[q] && col < xe[q]) ? invx[q] : 0.f;
#pragma unroll
            for (int p = 0; p < 5; p++) bins[p * 5 + q] += colsum[p] * wq;
        }
    }
#pragma unroll
    for (int t = 0; t < 25; t++) {
        float v = bins[t];
        v += __shfl_xor_sync(0xffffffffu, v, 16);
        v += __shfl_xor_sync(0xffffffffu, v, 8);
        v += __shfl_xor_sync(0xffffffffu, v, 4);
        v += __shfl_xor_sync(0xffffffffu, v, 2);
        v += __shfl_xor_sync(0xffffffffu, v, 1);
        bins[t] = v;
    }
    if (lane < 25) {
        float vout = 0.f;
#pragma unroll
        for (int t = 0; t < 25; t++)
            if (lane == t) vout = bins[t];
        obj[((long)br * OC + c) * 25 + lane] = vout;
    }
}

__global__ void copy_boxes_kernel(const float* __restrict__ boxes,
                                  float* __restrict__ out) {
    int i = blockIdx.x * blockDim.x + threadIdx.x;
    if (i < 640) out[i] = boxes[i];
}

// ---------------------------------------------------------------------------
extern "C" void kernel_launch(void* const* d_in, const int* in_sizes, int n_in,
                              void* d_out, int out_size) {
    const float* c3    = (const float*)d_in[0];
    const float* c4    = (const float*)d_in[1];
    const float* boxes = (const float*)d_in[2];
    const float* w     = (const float*)d_in[3];
    const float* bconv = (const float*)d_in[4];
    const float* gamma = (const float*)d_in[5];
    const float* beta  = (const float*)d_in[6];
    const float* mean  = (const float*)d_in[7];
    const float* var   = (const float*)d_in[8];

    float* out = (float*)d_out;
    float* obj = out;
    if (out_size >= 640 + 16 * 10 * 512 * 25) {
        copy_boxes_kernel<<<3, 256>>>(boxes, out);
        obj = out + 640;
    }

    cudaFuncSetAttribute(gemm_kernel, cudaFuncAttributeMaxDynamicSharedMemorySize,
                         GEMM_SMEM);

    wsplit_kernel<<<(OC * KD + 255) / 256, 256>>>(w);
    fuse_kernel<<<dim3(16, 24, 64), 256>>>(c3, c4);
    gemm_kernel<<<dim3(4, 512), 256, GEMM_SMEM>>>(bconv, gamma, beta, mean, var);
    pool_kernel<<<dim3(160, 64), 256>>>(boxes, obj);
}

// round 5
// speedup vs baseline: 2.8522x; 1.2228x over previous
#include <cuda_runtime.h>
#include <cuda_bf16.h>
#include <cstdint>

// ---------------------------------------------------------------------------
//   c3   : [16, 512, 64, 64] f32
//   c4   : [16,1024, 32, 32] f32
//   boxes: [16, 10, 4] f32
//   w    : [512, 1536] f32
//   out  : boxes (640 f32) ++ obj_blob [16,10,512,5,5]
// ---------------------------------------------------------------------------
#define OC   512
#define HW   4096
#define KD   1536

// Scratch (device globals — allocation-free)
// A packed: W in m16n8k8-tf32 A-fragment order. tile(mt,kt): 32 lanes x 4 f32.
//   lane l (r=l>>2, c=l&3): {W[mt*16+r][kt*8+c], W[..r+8][c], W[r][c+4], W[r+8][c+4]}
__device__ __align__(128) uint32_t g_wpack[OC * KD];            // 3 MB
// B packed: fusedT in B-fragment order. tile(nt,kt): 32 lanes x 2 f32.
//   lane l (n=l>>2, k=l&3): {F[nt*8+n][kt*8+k], F[..][k+4]}
__device__ __align__(128) uint32_t g_bpack[16L * HW * KD];      // 384 MB
__device__ __align__(128) float    g_attr [16L * OC * HW];      // 128 MB

// ---------------------------------------------------------------------------
// PTX helpers (baseline ISA only)
// ---------------------------------------------------------------------------
__device__ __forceinline__ uint32_t smem_u32(const void* p) {
    uint32_t a;
    asm("{ .reg .u64 t; cvta.to.shared.u64 t, %1; cvt.u32.u64 %0, t; }" : "=r"(a) : "l"(p));
    return a;
}
__device__ __forceinline__ void cp16(uint32_t dst, const void* src) {
    asm volatile("cp.async.cg.shared.global [%0], [%1], 16;" :: "r"(dst), "l"(src));
}
#define CP_COMMIT() asm volatile("cp.async.commit_group;" ::: "memory")
#define CP_WAIT0()  asm volatile("cp.async.wait_group 0;" ::: "memory")
#define CP_WAIT1()  asm volatile("cp.async.wait_group 1;" ::: "memory")

__device__ __forceinline__ uint32_t to_tf32(float f) {
    uint32_t r;
    asm("cvt.rna.tf32.f32 %0, %1;" : "=r"(r) : "f"(f));
    return r;
}
__device__ __forceinline__ void mma_tf32(float* c, const uint32_t* a,
                                         uint32_t b0, uint32_t b1) {
    asm volatile(
        "mma.sync.aligned.m16n8k8.row.col.f32.tf32.tf32.f32 "
        "{%0,%1,%2,%3}, {%4,%5,%6,%7}, {%8,%9}, {%0,%1,%2,%3};"
        : "+f"(c[0]), "+f"(c[1]), "+f"(c[2]), "+f"(c[3])
        : "r"(a[0]), "r"(a[1]), "r"(a[2]), "r"(a[3]), "r"(b0), "r"(b1));
}

// ---------------------------------------------------------------------------
// Kernel 0: pack W -> A-fragment order, tf32-rounded
// ---------------------------------------------------------------------------
__global__ void wpack_kernel(const float* __restrict__ w) {
    const int i = blockIdx.x * 256 + threadIdx.x;          // uint4 index
    if (i >= 32 * 192 * 32) return;                        // 6144 tiles x 32 lanes
    const int t = i >> 5, lane = i & 31;
    const int mt = t / 192, kt = t % 192;
    const int r = lane >> 2, c4 = lane & 3;
    const int o = mt * 16 + r, c = kt * 8 + c4;
    uint4 v;
    v.x = to_tf32(w[(long)o * KD + c]);
    v.y = to_tf32(w[(long)(o + 8) * KD + c]);
    v.z = to_tf32(w[(long)o * KD + c + 4]);
    v.w = to_tf32(w[(long)(o + 8) * KD + c + 4]);
    ((uint4*)g_wpack)[i] = v;
}

// ---------------------------------------------------------------------------
// Kernel 1: fused = concat(c3, bilinear2x(c4)) -> B-fragment-packed tf32
//   grid (16 b, 24 ctile, 64 h), block 256
// ---------------------------------------------------------------------------
__global__ __launch_bounds__(256) void fuse_kernel(const float* __restrict__ c3,
                                                   const float* __restrict__ c4) {
    __shared__ uint32_t s[64][65];                         // [w][c] tf32 bits
    const int b  = blockIdx.x;
    const int ct = blockIdx.y;
    const int h  = blockIdx.z;
    const int tid = threadIdx.x;
    const int c0 = ct * 64;

    const float syf = h * 0.5f - 0.25f;
    const float y0f = floorf(syf);
    const float fy  = syf - y0f;
    const int  iy0 = max(0, min(31, (int)y0f));
    const int  iy1 = max(0, min(31, (int)y0f + 1));

    for (int idx = tid; idx < 4096; idx += 256) {
        const int w = idx & 63;
        const int c = idx >> 6;
        const int cg = c0 + c;
        float v;
        if (cg < 512) {
            v = c3[(((long)(b * 512 + cg)) << 12) + h * 64 + w];
        } else {
            const int cc = cg - 512;
            const float* src = c4 + ((long)(b * 1024 + cc)) * 1024;
            const float sxf = w * 0.5f - 0.25f;
            const float x0f = floorf(sxf);
            const float fx  = sxf - x0f;
            const int ix0 = max(0, min(31, (int)x0f));
            const int ix1 = max(0, min(31, (int)x0f + 1));
            const float* r0 = src + iy0 * 32;
            const float* r1 = src + iy1 * 32;
            const float a  = r0[ix0] * (1.f - fx) + r0[ix1] * fx;
            const float bb = r1[ix0] * (1.f - fx) + r1[ix1] * fx;
            v = a * (1.f - fy) + bb * fy;
        }
        s[w][c] = to_tf32(v);
    }
    __syncthreads();

    // phase 2: write B-fragment-packed rows (8 f32 = 32B per (w, kt))
    for (int idx = tid; idx < 512; idx += 256) {
        const int w   = idx & 63;
        const int ktl = idx >> 6;                          // 0..7
        const uint32_t* row = &s[w][ktl * 8];
        uint4 lo, hi;                                      // permute k -> (k&3)*2+(k>>2)
        lo.x = row[0]; lo.y = row[4]; lo.z = row[1]; lo.w = row[5];
        hi.x = row[2]; hi.y = row[6]; hi.z = row[3]; hi.w = row[7];
        const long nt = (long)b * 512 + ((h * 64 + w) >> 3);
        const long basef = (nt * 192 + ct * 8 + ktl) * 64 + (w & 7) * 8;
        *(uint4*)(g_bpack + basef)     = lo;
        *(uint4*)(g_bpack + basef + 4) = hi;
    }
}

// ---------------------------------------------------------------------------
// Kernel 2: tf32 mma.sync GEMM  attr = relu(bn(W @ fusedT^T))
//   CTA 128x128, BK=32 double-buffered cp.async, 8 warps (2m x 4n),
//   warp tile 64x32, single tf32 pass, fragment-packed smem (no swizzle).
// ---------------------------------------------------------------------------
#define STG_BYTES 32768            // A 16KB + B 16KB per stage
#define B_OFF 16384
#define BN_OFF (2 * STG_BYTES)     // 65536
#define GEMM_SMEM (BN_OFF + 1024)

__global__ __launch_bounds__(256, 2)
void gemm_kernel(const float* __restrict__ bconv, const float* __restrict__ gamma,
                 const float* __restrict__ beta,  const float* __restrict__ mean,
                 const float* __restrict__ var) {
    extern __shared__ char smem[];
    const uint32_t sb = smem_u32(smem);
    const int tid  = threadIdx.x;
    const int wid  = tid >> 5, lane = tid & 31;
    const int wm   = wid >> 2;             // 0..1
    const int wn   = wid & 3;              // 0..3
    const int m0   = blockIdx.x * 128;
    const int ny   = blockIdx.y;
    const int bI   = ny >> 5;
    const int hw0  = (ny & 31) * 128;

    float* s_inv  = (float*)(smem + BN_OFF);
    float* s_bias = s_inv + 128;
    if (tid < 128) {
        const int o = m0 + tid;
        const float iv = gamma[o] * rsqrtf(var[o] + 1e-5f);
        s_inv[tid]  = iv;
        s_bias[tid] = (bconv[o] - mean[o]) * iv + beta[o];
    }

    const uint4* Wp = (const uint4*)g_wpack;   // tile(mt,kt) = 32 uint4
    const uint4* Bp = (const uint4*)g_bpack;   // tile(nt,kt) = 16 uint4
    const int mtb = blockIdx.x * 8;
    const long ntb = (long)bI * 512 + (ny & 31) * 16;

    // per-thread gmem/smem slots: 4 uint4 for A, 4 for B per stage
    long  aG[4], bG[4];
    uint32_t aS[4], bS[4];
#pragma unroll
    for (int j = 0; j < 4; ++j) {
        const int u = tid + j * 256;
        { // A: u -> (mt_l = u>>7, kt_l = (u>>5)&3, lane = u&31)
            const int mt_l = u >> 7, kt_l = (u >> 5) & 3, ln = u & 31;
            aG[j] = ((long)(mtb + mt_l) * 192 + kt_l) * 32 + ln;
            aS[j] = (uint32_t)u * 16;
        }
        { // B: u -> (nt_l = u>>6, kt_l = (u>>4)&3, w = u&15)
            const int nt_l = u >> 6, kt_l = (u >> 4) & 3, w = u & 15;
            bG[j] = ((ntb + nt_l) * 192 + kt_l) * 16 + w;
            bS[j] = (uint32_t)(B_OFF + u * 16);
        }
    }

    auto load_stage = [&](int buf, int t) {
        const uint32_t stg = sb + buf * STG_BYTES;
#pragma unroll
        for (int j = 0; j < 4; ++j) {
            cp16(stg + aS[j], Wp + aG[j] + (long)t * 128);   // 4 kt x 32 lanes
            cp16(stg + bS[j], Bp + bG[j] + (long)t * 64);    // 4 kt x 16
        }
    };

    float acc[4][4][4];
#pragma unroll
    for (int i = 0; i < 4; i++)
#pragma unroll
        for (int j = 0; j < 4; j++)
#pragma unroll
            for (int k = 0; k < 4; k++) acc[i][j][k] = 0.f;

    load_stage(0, 0);
    CP_COMMIT();

    for (int t = 0; t < 48; ++t) {
        if (t + 1 < 48) { load_stage((t + 1) & 1, t + 1); CP_COMMIT(); CP_WAIT1(); }
        else            { CP_WAIT0(); }
        __syncthreads();

        const uint32_t stg = sb + (t & 1) * STG_BYTES;
#pragma unroll
        for (int kg = 0; kg < 4; ++kg) {
            uint32_t bf[4][2];
#pragma unroll
            for (int nf = 0; nf < 4; ++nf) {
                const uint32_t ba = stg + B_OFF +
                    (uint32_t)(((wn * 4 + nf) * 4 + kg) * 256 + lane * 8);
                asm volatile("ld.shared.v2.b32 {%0,%1}, [%2];"
                             : "=r"(bf[nf][0]), "=r"(bf[nf][1]) : "r"(ba));
            }
#pragma unroll
            for (int mf = 0; mf < 4; ++mf) {
                uint32_t af[4];
                const uint32_t aa = stg +
                    (uint32_t)((((wm * 4 + mf) * 4 + kg) * 32 + lane) * 16);
                asm volatile("ld.shared.v4.b32 {%0,%1,%2,%3}, [%4];"
                             : "=r"(af[0]), "=r"(af[1]), "=r"(af[2]), "=r"(af[3])
                             : "r"(aa));
#pragma unroll
                for (int nf = 0; nf < 4; ++nf)
                    mma_tf32(acc[mf][nf], af, bf[nf][0], bf[nf][1]);
            }
        }
        __syncthreads();
    }

    // epilogue: BN + relu, direct stores
    const int g = lane >> 2, tq = lane & 3;
    float* attr = g_attr + ((long)bI * OC + m0) * HW + hw0;
#pragma unroll
    for (int mf = 0; mf < 4; ++mf) {
        const int ml0 = wm * 64 + mf * 16 + g;
        const int ml1 = ml0 + 8;
        const float i0 = s_inv[ml0], z0 = s_bias[ml0];
        const float i1 = s_inv[ml1], z1 = s_bias[ml1];
#pragma unroll
        for (int nf = 0; nf < 4; ++nf) {
            const int n = wn * 32 + nf * 8 + 2 * tq;
            float2 v0 = make_float2(fmaxf(acc[mf][nf][0] * i0 + z0, 0.f),
                                    fmaxf(acc[mf][nf][1] * i0 + z0, 0.f));
            float2 v1 = make_float2(fmaxf(acc[mf][nf][2] * i1 + z1, 0.f),
                                    fmaxf(acc[mf][nf][3] * i1 + z1, 0.f));
            *(float2*)(attr + (long)ml0 * HW + n) = v0;
            *(float2*)(attr + (long)ml1 * HW + n) = v1;
        }
    }
}

// ---------------------------------------------------------------------------
// Kernel 3: ROI adaptive-avg-pool 5x5.  grid (160, 64): warp = (box, channel)
// ---------------------------------------------------------------------------
__global__ __launch_bounds__(256) void pool_kernel(const float* __restrict__ boxes,
                                                   float* __restrict__ obj) {
    const int br = blockIdx.x;
    const int b  = br / 10;
    const float* bx = boxes + br * 4;

    int x1 = min(63, max(0, (int)floorf(bx[0] * 0.125f)));
    int y1 = min(63, max(0, (int)floorf(bx[1] * 0.125f)));
    int x2 = min(63, max(0, (int)ceilf (bx[2] * 0.125f)));
    int y2 = min(63, max(0, (int)ceilf (bx[3] * 0.125f)));
    if (x2 <= x1) x2 = min(x1 + 1, 64);
    if (y2 <= y1) y2 = min(y1 + 1, 64);
    const int Lx = x2 - x1, Ly = y2 - y1;

    int xs[5], xe[5], ys[5], ye[5];
    float invx[5], invy[5];
#pragma unroll
    for (int k = 0; k < 5; k++) {
        xs[k] = x1 + (k * Lx) / 5;
        xe[k] = x1 + ((k + 1) * Lx + 4) / 5;
        ys[k] = y1 + (k * Ly) / 5;
        ye[k] = y1 + ((k + 1) * Ly + 4) / 5;
        invx[k] = 1.f / (float)(xe[k] - xs[k]);
        invy[k] = 1.f / (float)(ye[k] - ys[k]);
    }

    const int warp = threadIdx.x >> 5, lane = threadIdx.x & 31;
    const int c = blockIdx.y * 8 + warp;
    const float* ch = g_attr + ((long)b * OC + c) * HW;

    float bins[25];
#pragma unroll
    for (int t = 0; t < 25; t++) bins[t] = 0.f;

    for (int cw = 0; cw < Lx; cw += 32) {
        const int  col = x1 + cw + lane;
        const bool act = (cw + lane) < Lx;
        float colsum[5] = {0.f, 0.f, 0.f, 0.f, 0.f};
        if (act) {
#pragma unroll 4
            for (int h = y1; h < y2; h++) {
                const float v = __ldg(ch + h * 64 + col);
#pragma unroll
                for (int p = 0; p < 5; p++)
                    if (h >= ys[p] && h < ye[p]) colsum[p] += v * invy[p];
            }
        }
#pragma unroll
        for (int q = 0; q < 5; q++) {
            const float wq = (act && col >= xs[q] && col < xe[q]) ? invx[q] : 0.f;
#pragma unroll
            for (int p = 0; p < 5; p++) bins[p * 5 + q] += colsum[p] * wq;
        }
    }
#pragma unroll
    for (int t = 0; t < 25; t++) {
        float v = bins[t];
        v += __shfl_xor_sync(0xffffffffu, v, 16);
        v += __shfl_xor_sync(0xffffffffu, v, 8);
        v += __shfl_xor_sync(0xffffffffu, v, 4);
        v += __shfl_xor_sync(0xffffffffu, v, 2);
        v += __shfl_xor_sync(0xffffffffu, v, 1);
        bins[t] = v;
    }
    if (lane < 25) {
        float vout = 0.f;
#pragma unroll
        for (int t = 0; t < 25; t++)
            if (lane == t) vout = bins[t];
        obj[((long)br * OC + c) * 25 + lane] = vout;
    }
}

__global__ void copy_boxes_kernel(const float* __restrict__ boxes,
                                  float* __restrict__ out) {
    int i = blockIdx.x * blockDim.x + threadIdx.x;
    if (i < 640) out[i] = boxes[i];
}

// ---------------------------------------------------------------------------
extern "C" void kernel_launch(void* const* d_in, const int* in_sizes, int n_in,
                              void* d_out, int out_size) {
    const float* c3    = (const float*)d_in[0];
    const float* c4    = (const float*)d_in[1];
    const float* boxes = (const float*)d_in[2];
    const float* w     = (const float*)d_in[3];
    const float* bconv = (const float*)d_in[4];
    const float* gamma = (const float*)d_in[5];
    const float* beta  = (const float*)d_in[6];
    const float* mean  = (const float*)d_in[7];
    const float* var   = (const float*)d_in[8];

    float* out = (float*)d_out;
    float* obj = out;
    if (out_size >= 640 + 16 * 10 * 512 * 25) {
        copy_boxes_kernel<<<3, 256>>>(boxes, out);
        obj = out + 640;
    }

    cudaFuncSetAttribute(gemm_kernel, cudaFuncAttributeMaxDynamicSharedMemorySize,
                         GEMM_SMEM);

    wpack_kernel<<<(32 * 192 * 32 + 255) / 256, 256>>>(w);
    fuse_kernel<<<dim3(16, 24, 64), 256>>>(c3, c4);
    gemm_kernel<<<dim3(4, 512), 256, GEMM_SMEM>>>(bconv, gamma, beta, mean, var);
    pool_kernel<<<dim3(160, 64), 256>>>(boxes, obj);
}

// round 6
// speedup vs baseline: 3.9241x; 1.3758x over previous
#include <cuda_runtime.h>
#include <cuda_fp16.h>
#include <cstdint>

// ---------------------------------------------------------------------------
//   c3   : [16, 512, 64, 64] f32
//   c4   : [16,1024, 32, 32] f32
//   boxes: [16, 10, 4] f32
//   w    : [512, 1536] f32
//   out  : boxes (640 f32) ++ obj_blob [16,10,512,5,5]
// ---------------------------------------------------------------------------
#define OC   512
#define HW   4096
#define KD   1536
#define NKT  96                    // K / 16

// Scratch (device globals — allocation-free)
// A packed: W in m16n8k16-fp16 A-fragment order.
//   tile(mt 0..31, kt 0..95): 32 lanes x 4 uint32 (each = 2 fp16) = 512B
//   lane l (r=l>>2, c=l&3):
//     a0={W[mt*16+r][kt*16+2c, +1]}  a1={r+8}  a2={k+8}  a3={r+8,k+8}
__device__ __align__(128) uint32_t g_wpack[OC * KD / 2];          // 1.5 MB
// B packed: fusedT in B-fragment order.
//   tile(nt 0..8191, kt 0..95): 32 lanes x 2 uint32 = 256B
//   lane l (n=l>>2, r=l&3): b0={F[nt*8+n][kt*16+2r, +1]}  b1={k+8}
__device__ __align__(128) uint32_t g_bpack[16L * HW * KD / 2];    // 192 MB
__device__ __align__(128) float    g_attr [16L * OC * HW];        // 128 MB

// ---------------------------------------------------------------------------
// PTX helpers (baseline ISA only)
// ---------------------------------------------------------------------------
__device__ __forceinline__ uint32_t smem_u32(const void* p) {
    uint32_t a;
    asm("{ .reg .u64 t; cvta.to.shared.u64 t, %1; cvt.u32.u64 %0, t; }" : "=r"(a) : "l"(p));
    return a;
}
__device__ __forceinline__ void cp16(uint32_t dst, const void* src) {
    asm volatile("cp.async.cg.shared.global [%0], [%1], 16;" :: "r"(dst), "l"(src));
}
#define CP_COMMIT() asm volatile("cp.async.commit_group;" ::: "memory")
#define CP_WAIT0()  asm volatile("cp.async.wait_group 0;" ::: "memory")
#define CP_WAIT1()  asm volatile("cp.async.wait_group 1;" ::: "memory")

__device__ __forceinline__ uint32_t pack_h2(float lo, float hi) {
    __half2 h = __floats2half2_rn(lo, hi);
    return *(uint32_t*)&h;
}
__device__ __forceinline__ void mma_f16(float* c, const uint32_t* a,
                                        uint32_t b0, uint32_t b1) {
    asm volatile(
        "mma.sync.aligned.m16n8k16.row.col.f32.f16.f16.f32 "
        "{%0,%1,%2,%3}, {%4,%5,%6,%7}, {%8,%9}, {%0,%1,%2,%3};"
        : "+f"(c[0]), "+f"(c[1]), "+f"(c[2]), "+f"(c[3])
        : "r"(a[0]), "r"(a[1]), "r"(a[2]), "r"(a[3]), "r"(b0), "r"(b1));
}

// ---------------------------------------------------------------------------
// Kernel 0: pack W -> fp16 A-fragment order
// ---------------------------------------------------------------------------
__global__ void wpack_kernel(const float* __restrict__ w) {
    const int i = blockIdx.x * 256 + threadIdx.x;          // lane-entry index
    if (i >= 32 * NKT * 32) return;
    const int t = i >> 5, lane = i & 31;
    const int mt = t / NKT, kt = t % NKT;
    const int r = lane >> 2, c = lane & 3;
    const float* w0 = w + (long)(mt * 16 + r) * KD + kt * 16 + 2 * c;
    const float* w8 = w0 + 8 * KD;
    uint4 v;
    v.x = pack_h2(w0[0], w0[1]);
    v.y = pack_h2(w8[0], w8[1]);
    v.z = pack_h2(w0[8], w0[9]);
    v.w = pack_h2(w8[8], w8[9]);
    ((uint4*)g_wpack)[i] = v;
}

// ---------------------------------------------------------------------------
// Kernel 1: fused = concat(c3, bilinear2x(c4)) -> fp16 B-fragment-packed
//   grid (16 b, 24 ctile, 64 h), block 256.  ctile = 64 channels = 4 kt16.
// ---------------------------------------------------------------------------
__global__ __launch_bounds__(256) void fuse_kernel(const float* __restrict__ c3,
                                                   const float* __restrict__ c4) {
    __shared__ float s[64][65];                            // [w][c]
    const int b  = blockIdx.x;
    const int ct = blockIdx.y;
    const int h  = blockIdx.z;
    const int tid = threadIdx.x;
    const int c0 = ct * 64;

    const float syf = h * 0.5f - 0.25f;
    const float y0f = floorf(syf);
    const float fy  = syf - y0f;
    const int  iy0 = max(0, min(31, (int)y0f));
    const int  iy1 = max(0, min(31, (int)y0f + 1));

    for (int idx = tid; idx < 4096; idx += 256) {
        const int w = idx & 63;
        const int c = idx >> 6;
        const int cg = c0 + c;
        float v;
        if (cg < 512) {
            v = c3[(((long)(b * 512 + cg)) << 12) + h * 64 + w];
        } else {
            const int cc = cg - 512;
            const float* src = c4 + ((long)(b * 1024 + cc)) * 1024;
            const float sxf = w * 0.5f - 0.25f;
            const float x0f = floorf(sxf);
            const float fx  = sxf - x0f;
            const int ix0 = max(0, min(31, (int)x0f));
            const int ix1 = max(0, min(31, (int)x0f + 1));
            const float* r0 = src + iy0 * 32;
            const float* r1 = src + iy1 * 32;
            const float a  = r0[ix0] * (1.f - fx) + r0[ix1] * fx;
            const float bb = r1[ix0] * (1.f - fx) + r1[ix1] * fx;
            v = a * (1.f - fy) + bb * fy;
        }
        s[w][c] = v;
    }
    __syncthreads();

    // phase 2: each thread packs one (w, kt16) -> 8 uint32 (4 B-lanes x 2 regs)
    {
        const int w   = tid & 63;
        const int ktl = tid >> 6;                          // 0..3
        const float* row = &s[w][ktl * 16];
        uint4 lo, hi;                                      // lane=(w&7)*4+r, off lane*2+reg
        lo.x = pack_h2(row[0], row[1]);   lo.y = pack_h2(row[8],  row[9]);
        lo.z = pack_h2(row[2], row[3]);   lo.w = pack_h2(row[10], row[11]);
        hi.x = pack_h2(row[4], row[5]);   hi.y = pack_h2(row[12], row[13]);
        hi.z = pack_h2(row[6], row[7]);   hi.w = pack_h2(row[14], row[15]);
        const long nt  = (long)b * 512 + ((h * 64 + w) >> 3);
        const long base = (nt * NKT + ct * 4 + ktl) * 64 + (w & 7) * 8;
        *(uint4*)(g_bpack + base)     = lo;
        *(uint4*)(g_bpack + base + 4) = hi;
    }
}

// ---------------------------------------------------------------------------
// Kernel 2: fp16 mma.sync GEMM  attr = relu(bn(W @ fusedT^T))
//   CTA 128x128, BK=32 (2 kt16) double-buffered cp.async, 8 warps (2m x 4n),
//   warp tile 64x32, fragment-packed smem (no swizzle, conflict-free).
// ---------------------------------------------------------------------------
#define STG_BYTES 16384            // A 8KB + B 8KB per stage
#define B_OFF 8192
#define BN_OFF (2 * STG_BYTES)     // 32768
#define GEMM_SMEM (BN_OFF + 1024)

__global__ __launch_bounds__(256, 2)
void gemm_kernel(const float* __restrict__ bconv, const float* __restrict__ gamma,
                 const float* __restrict__ beta,  const float* __restrict__ mean,
                 const float* __restrict__ var) {
    extern __shared__ char smem[];
    const uint32_t sb = smem_u32(smem);
    const int tid  = threadIdx.x;
    const int wid  = tid >> 5, lane = tid & 31;
    const int wm   = wid >> 2;             // 0..1
    const int wn   = wid & 3;              // 0..3
    const int m0   = blockIdx.x * 128;
    const int ny   = blockIdx.y;
    const int bI   = ny >> 5;
    const int hw0  = (ny & 31) * 128;

    float* s_inv  = (float*)(smem + BN_OFF);
    float* s_bias = s_inv + 128;
    if (tid < 128) {
        const int o = m0 + tid;
        const float iv = gamma[o] * rsqrtf(var[o] + 1e-5f);
        s_inv[tid]  = iv;
        s_bias[tid] = (bconv[o] - mean[o]) * iv + beta[o];
    }

    const uint4* Wp = (const uint4*)g_wpack;   // tile(mt,kt) = 32 uint4
    const uint4* Bp = (const uint4*)g_bpack;   // tile(nt,kt) = 16 uint4
    const int  mtb = blockIdx.x * 8;
    const long ntb = (long)bI * 512 + (ny & 31) * 16;

    // per-thread load slots: 2 uint4 for A, 2 for B per stage
    long  aG[2], bG[2];
    uint32_t aS[2], bS[2];
#pragma unroll
    for (int j = 0; j < 2; ++j) {
        const int u = tid + j * 256;           // 0..511
        { // A chunk u -> (mt_l = u>>6, kt_l = (u>>5)&1, ln = u&31)
            const int mt_l = u >> 6, kt_l = (u >> 5) & 1, ln = u & 31;
            aG[j] = ((long)(mtb + mt_l) * NKT + kt_l) * 32 + ln;
            aS[j] = (uint32_t)u * 16;
        }
        { // B chunk u -> (nt_l = u>>5, kt_l = (u>>4)&1, p = u&15)
            const int nt_l = u >> 5, kt_l = (u >> 4) & 1, p = u & 15;
            bG[j] = ((ntb + nt_l) * NKT + kt_l) * 16 + p;
            bS[j] = (uint32_t)(B_OFF + u * 16);
        }
    }

    auto load_stage = [&](int buf, int t) {
        const uint32_t stg = sb + buf * STG_BYTES;
#pragma unroll
        for (int j = 0; j < 2; ++j) {
            cp16(stg + aS[j], Wp + aG[j] + (long)t * 64);   // 2 kt x 32 lanes
            cp16(stg + bS[j], Bp + bG[j] + (long)t * 32);   // 2 kt x 16
        }
    };

    float acc[4][4][4];
#pragma unroll
    for (int i = 0; i < 4; i++)
#pragma unroll
        for (int j = 0; j < 4; j++)
#pragma unroll
            for (int k = 0; k < 4; k++) acc[i][j][k] = 0.f;

    load_stage(0, 0);
    CP_COMMIT();

    for (int t = 0; t < 48; ++t) {
        if (t + 1 < 48) { load_stage((t + 1) & 1, t + 1); CP_COMMIT(); CP_WAIT1(); }
        else            { CP_WAIT0(); }
        __syncthreads();

        const uint32_t stg = sb + (t & 1) * STG_BYTES;
#pragma unroll
        for (int kg = 0; kg < 2; ++kg) {
            uint32_t bf[4][2];
#pragma unroll
            for (int nf = 0; nf < 4; ++nf) {
                const uint32_t ba = stg + B_OFF +
                    (uint32_t)(((wn * 4 + nf) * 2 + kg) * 256 + lane * 8);
                asm volatile("ld.shared.v2.b32 {%0,%1}, [%2];"
                             : "=r"(bf[nf][0]), "=r"(bf[nf][1]) : "r"(ba));
            }
#pragma unroll
            for (int mf = 0; mf < 4; ++mf) {
                uint32_t af[4];
                const uint32_t aa = stg +
                    (uint32_t)((((wm * 4 + mf) * 2 + kg) * 32 + lane) * 16);
                asm volatile("ld.shared.v4.b32 {%0,%1,%2,%3}, [%4];"
                             : "=r"(af[0]), "=r"(af[1]), "=r"(af[2]), "=r"(af[3])
                             : "r"(aa));
#pragma unroll
                for (int nf = 0; nf < 4; ++nf)
                    mma_f16(acc[mf][nf], af, bf[nf][0], bf[nf][1]);
            }
        }
        __syncthreads();
    }

    // epilogue: BN + relu, direct stores
    const int g = lane >> 2, tq = lane & 3;
    float* attr = g_attr + ((long)bI * OC + m0) * HW + hw0;
#pragma unroll
    for (int mf = 0; mf < 4; ++mf) {
        const int ml0 = wm * 64 + mf * 16 + g;
        const int ml1 = ml0 + 8;
        const float i0 = s_inv[ml0], z0 = s_bias[ml0];
        const float i1 = s_inv[ml1], z1 = s_bias[ml1];
#pragma unroll
        for (int nf = 0; nf < 4; ++nf) {
            const int n = wn * 32 + nf * 8 + 2 * tq;
            float2 v0 = make_float2(fmaxf(acc[mf][nf][0] * i0 + z0, 0.f),
                                    fmaxf(acc[mf][nf][1] * i0 + z0, 0.f));
            float2 v1 = make_float2(fmaxf(acc[mf][nf][2] * i1 + z1, 0.f),
                                    fmaxf(acc[mf][nf][3] * i1 + z1, 0.f));
            *(float2*)(attr + (long)ml0 * HW + n) = v0;
            *(float2*)(attr + (long)ml1 * HW + n) = v1;
        }
    }
}

// ---------------------------------------------------------------------------
// Kernel 3: ROI adaptive-avg-pool 5x5.  grid (160, 64): warp = (box, channel)
// ---------------------------------------------------------------------------
__global__ __launch_bounds__(256) void pool_kernel(const float* __restrict__ boxes,
                                                   float* __restrict__ obj) {
    const int br = blockIdx.x;
    const int b  = br / 10;
    const float* bx = boxes + br * 4;

    int x1 = min(63, max(0, (int)floorf(bx[0] * 0.125f)));
    int y1 = min(63, max(0, (int)floorf(bx[1] * 0.125f)));
    int x2 = min(63, max(0, (int)ceilf (bx[2] * 0.125f)));
    int y2 = min(63, max(0, (int)ceilf (bx[3] * 0.125f)));
    if (x2 <= x1) x2 = min(x1 + 1, 64);
    if (y2 <= y1) y2 = min(y1 + 1, 64);
    const int Lx = x2 - x1, Ly = y2 - y1;

    int xs[5], xe[5], ys[5], ye[5];
    float invx[5], invy[5];
#pragma unroll
    for (int k = 0; k < 5; k++) {
        xs[k] = x1 + (k * Lx) / 5;
        xe[k] = x1 + ((k + 1) * Lx + 4) / 5;
        ys[k] = y1 + (k * Ly) / 5;
        ye[k] = y1 + ((k + 1) * Ly + 4) / 5;
        invx[k] = 1.f / (float)(xe[k] - xs[k]);
        invy[k] = 1.f / (float)(ye[k] - ys[k]);
    }

    const int warp = threadIdx.x >> 5, lane = threadIdx.x & 31;
    const int c = blockIdx.y * 8 + warp;
    const float* ch = g_attr + ((long)b * OC + c) * HW;

    float bins[25];
#pragma unroll
    for (int t = 0; t < 25; t++) bins[t] = 0.f;

    for (int cw = 0; cw < Lx; cw += 32) {
        const int  col = x1 + cw + lane;
        const bool act = (cw + lane) < Lx;
        float colsum[5] = {0.f, 0.f, 0.f, 0.f, 0.f};
        if (act) {
#pragma unroll 4
            for (int h = y1; h < y2; h++) {
                const float v = __ldg(ch + h * 64 + col);
#pragma unroll
                for (int p = 0; p < 5; p++)
                    if (h >= ys[p] && h < ye[p]) colsum[p] += v * invy[p];
            }
        }
#pragma unroll
        for (int q = 0; q < 5; q++) {
            const float wq = (act && col >= xs[q] && col < xe[q]) ? invx[q] : 0.f;
#pragma unroll
            for (int p = 0; p < 5; p++) bins[p * 5 + q] += colsum[p] * wq;
        }
    }
#pragma unroll
    for (int t = 0; t < 25; t++) {
        float v = bins[t];
        v += __shfl_xor_sync(0xffffffffu, v, 16);
        v += __shfl_xor_sync(0xffffffffu, v, 8);
        v += __shfl_xor_sync(0xffffffffu, v, 4);
        v += __shfl_xor_sync(0xffffffffu, v, 2);
        v += __shfl_xor_sync(0xffffffffu, v, 1);
        bins[t] = v;
    }
    if (lane < 25) {
        float vout = 0.f;
#pragma unroll
        for (int t = 0; t < 25; t++)
            if (lane == t) vout = bins[t];
        obj[((long)br * OC + c) * 25 + lane] = vout;
    }
}

__global__ void copy_boxes_kernel(const float* __restrict__ boxes,
                                  float* __restrict__ out) {
    int i = blockIdx.x * blockDim.x + threadIdx.x;
    if (i < 640) out[i] = boxes[i];
}

// ---------------------------------------------------------------------------
extern "C" void kernel_launch(void* const* d_in, const int* in_sizes, int n_in,
                              void* d_out, int out_size) {
    const float* c3    = (const float*)d_in[0];
    const float* c4    = (const float*)d_in[1];
    const float* boxes = (const float*)d_in[2];
    const float* w     = (const float*)d_in[3];
    const float* bconv = (const float*)d_in[4];
    const float* gamma = (const float*)d_in[5];
    const float* beta  = (const float*)d_in[6];
    const float* mean  = (const float*)d_in[7];
    const float* var   = (const float*)d_in[8];

    float* out = (float*)d_out;
    float* obj = out;
    if (out_size >= 640 + 16 * 10 * 512 * 25) {
        copy_boxes_kernel<<<3, 256>>>(boxes, out);
        obj = out + 640;
    }

    cudaFuncSetAttribute(gemm_kernel, cudaFuncAttributeMaxDynamicSharedMemorySize,
                         GEMM_SMEM);

    wpack_kernel<<<(32 * NKT * 32 + 255) / 256, 256>>>(w);
    fuse_kernel<<<dim3(16, 24, 64), 256>>>(c3, c4);
    gemm_kernel<<<dim3(4, 512), 256, GEMM_SMEM>>>(bconv, gamma, beta, mean, var);
    pool_kernel<<<dim3(160, 64), 256>>>(boxes, obj);
}

// round 7
// speedup vs baseline: 4.1269x; 1.0517x over previous
#include <cuda_runtime.h>
#include <cuda_fp16.h>
#include <cstdint>

// ---------------------------------------------------------------------------
//   c3   : [16, 512, 64, 64] f32
//   c4   : [16,1024, 32, 32] f32
//   boxes: [16, 10, 4] f32
//   w    : [512, 1536] f32
//   out  : boxes (640 f32) ++ obj_blob [16,10,512,5,5]
// ---------------------------------------------------------------------------
#define OC   512
#define HW   4096
#define KD   1536
#define NKT  96                    // K / 16

// Scratch (device globals — allocation-free)
__device__ __align__(128) uint32_t g_wpack[OC * KD / 2];          // 1.5 MB
__device__ __align__(128) uint32_t g_bpack[16L * HW * KD / 2];    // 192 MB
__device__ __align__(128) __half   g_attrh[16L * OC * HW + 256];  // 64 MB fp16

// ---------------------------------------------------------------------------
// PTX helpers (baseline ISA only)
// ---------------------------------------------------------------------------
__device__ __forceinline__ uint32_t smem_u32(const void* p) {
    uint32_t a;
    asm("{ .reg .u64 t; cvta.to.shared.u64 t, %1; cvt.u32.u64 %0, t; }" : "=r"(a) : "l"(p));
    return a;
}
__device__ __forceinline__ void cp16(uint32_t dst, const void* src) {
    asm volatile("cp.async.cg.shared.global [%0], [%1], 16;" :: "r"(dst), "l"(src));
}
#define CP_COMMIT() asm volatile("cp.async.commit_group;" ::: "memory")
#define CP_WAIT2()  asm volatile("cp.async.wait_group 2;" ::: "memory")

__device__ __forceinline__ uint32_t pack_h2(float lo, float hi) {
    __half2 h = __floats2half2_rn(lo, hi);
    return *(uint32_t*)&h;
}
__device__ __forceinline__ void mma_f16(float* c, const uint32_t* a,
                                        uint32_t b0, uint32_t b1) {
    asm volatile(
        "mma.sync.aligned.m16n8k16.row.col.f32.f16.f16.f32 "
        "{%0,%1,%2,%3}, {%4,%5,%6,%7}, {%8,%9}, {%0,%1,%2,%3};"
        : "+f"(c[0]), "+f"(c[1]), "+f"(c[2]), "+f"(c[3])
        : "r"(a[0]), "r"(a[1]), "r"(a[2]), "r"(a[3]), "r"(b0), "r"(b1));
}

// ---------------------------------------------------------------------------
// Kernel 0: pack W -> fp16 A-fragment order (m16n8k16 layout)
// ---------------------------------------------------------------------------
__global__ void wpack_kernel(const float* __restrict__ w) {
    const int i = blockIdx.x * 256 + threadIdx.x;
    if (i >= 32 * NKT * 32) return;
    const int t = i >> 5, lane = i & 31;
    const int mt = t / NKT, kt = t % NKT;
    const int r = lane >> 2, c = lane & 3;
    const float* w0 = w + (long)(mt * 16 + r) * KD + kt * 16 + 2 * c;
    const float* w8 = w0 + 8 * KD;
    uint4 v;
    v.x = pack_h2(w0[0], w0[1]);
    v.y = pack_h2(w8[0], w8[1]);
    v.z = pack_h2(w0[8], w0[9]);
    v.w = pack_h2(w8[8], w8[9]);
    ((uint4*)g_wpack)[i] = v;
}

// ---------------------------------------------------------------------------
// Kernel 1: fused = concat(c3, bilinear2x(c4)) -> fp16 B-fragment-packed
//   grid (16 b, 24 ctile, 64 h), block 256.
// ---------------------------------------------------------------------------
__global__ __launch_bounds__(256) void fuse_kernel(const float* __restrict__ c3,
                                                   const float* __restrict__ c4) {
    __shared__ float s[64][65];
    const int b  = blockIdx.x;
    const int ct = blockIdx.y;
    const int h  = blockIdx.z;
    const int tid = threadIdx.x;
    const int c0 = ct * 64;

    const float syf = h * 0.5f - 0.25f;
    const float y0f = floorf(syf);
    const float fy  = syf - y0f;
    const int  iy0 = max(0, min(31, (int)y0f));
    const int  iy1 = max(0, min(31, (int)y0f + 1));

    for (int idx = tid; idx < 4096; idx += 256) {
        const int w = idx & 63;
        const int c = idx >> 6;
        const int cg = c0 + c;
        float v;
        if (cg < 512) {
            v = c3[(((long)(b * 512 + cg)) << 12) + h * 64 + w];
        } else {
            const int cc = cg - 512;
            const float* src = c4 + ((long)(b * 1024 + cc)) * 1024;
            const float sxf = w * 0.5f - 0.25f;
            const float x0f = floorf(sxf);
            const float fx  = sxf - x0f;
            const int ix0 = max(0, min(31, (int)x0f));
            const int ix1 = max(0, min(31, (int)x0f + 1));
            const float* r0 = src + iy0 * 32;
            const float* r1 = src + iy1 * 32;
            const float a  = r0[ix0] * (1.f - fx) + r0[ix1] * fx;
            const float bb = r1[ix0] * (1.f - fx) + r1[ix1] * fx;
            v = a * (1.f - fy) + bb * fy;
        }
        s[w][c] = v;
    }
    __syncthreads();

    {
        const int w   = tid & 63;
        const int ktl = tid >> 6;                          // 0..3
        const float* row = &s[w][ktl * 16];
        uint4 lo, hi;
        lo.x = pack_h2(row[0], row[1]);   lo.y = pack_h2(row[8],  row[9]);
        lo.z = pack_h2(row[2], row[3]);   lo.w = pack_h2(row[10], row[11]);
        hi.x = pack_h2(row[4], row[5]);   hi.y = pack_h2(row[12], row[13]);
        hi.z = pack_h2(row[6], row[7]);   hi.w = pack_h2(row[14], row[15]);
        const long nt  = (long)b * 512 + ((h * 64 + w) >> 3);
        const long base = (nt * NKT + ct * 4 + ktl) * 64 + (w & 7) * 8;
        *(uint4*)(g_bpack + base)     = lo;
        *(uint4*)(g_bpack + base + 4) = hi;
    }
}

// ---------------------------------------------------------------------------
// Kernel 2: fp16 mma.sync GEMM, 4-stage single-sync cp.async pipeline
//   CTA 128x128, BK=32, 8 warps (2m x 4n), warp tile 64x32.
// ---------------------------------------------------------------------------
#define STAGES    4
#define STG_BYTES 16384            // A 8KB + B 8KB per stage
#define B_OFF 8192
#define BN_OFF (STAGES * STG_BYTES)       // 65536
#define GEMM_SMEM (BN_OFF + 1024)

__global__ __launch_bounds__(256, 2)
void gemm_kernel(const float* __restrict__ bconv, const float* __restrict__ gamma,
                 const float* __restrict__ beta,  const float* __restrict__ mean,
                 const float* __restrict__ var) {
    extern __shared__ char smem[];
    const uint32_t sb = smem_u32(smem);
    const int tid  = threadIdx.x;
    const int wid  = tid >> 5, lane = tid & 31;
    const int wm   = wid >> 2;
    const int wn   = wid & 3;
    const int m0   = blockIdx.x * 128;
    const int ny   = blockIdx.y;
    const int bI   = ny >> 5;
    const int hw0  = (ny & 31) * 128;

    float* s_inv  = (float*)(smem + BN_OFF);
    float* s_bias = s_inv + 128;
    if (tid < 128) {
        const int o = m0 + tid;
        const float iv = gamma[o] * rsqrtf(var[o] + 1e-5f);
        s_inv[tid]  = iv;
        s_bias[tid] = (bconv[o] - mean[o]) * iv + beta[o];
    }

    const uint4* Wp = (const uint4*)g_wpack;
    const uint4* Bp = (const uint4*)g_bpack;
    const int  mtb = blockIdx.x * 8;
    const long ntb = (long)bI * 512 + (ny & 31) * 16;

    long  aG[2], bG[2];
    uint32_t aS[2], bS[2];
#pragma unroll
    for (int j = 0; j < 2; ++j) {
        const int u = tid + j * 256;
        {
            const int mt_l = u >> 6, kt_l = (u >> 5) & 1, ln = u & 31;
            aG[j] = ((long)(mtb + mt_l) * NKT + kt_l) * 32 + ln;
            aS[j] = (uint32_t)u * 16;
        }
        {
            const int nt_l = u >> 5, kt_l = (u >> 4) & 1, p = u & 15;
            bG[j] = ((ntb + nt_l) * NKT + kt_l) * 16 + p;
            bS[j] = (uint32_t)(B_OFF + u * 16);
        }
    }

    auto load_stage = [&](int buf, int t) {
        const uint32_t stg = sb + buf * STG_BYTES;
#pragma unroll
        for (int j = 0; j < 2; ++j) {
            cp16(stg + aS[j], Wp + aG[j] + (long)t * 64);
            cp16(stg + bS[j], Bp + bG[j] + (long)t * 32);
        }
    };

    float acc[4][4][4];
#pragma unroll
    for (int i = 0; i < 4; i++)
#pragma unroll
        for (int j = 0; j < 4; j++)
#pragma unroll
            for (int k = 0; k < 4; k++) acc[i][j][k] = 0.f;

    // prologue: 3 stages in flight
#pragma unroll
    for (int s = 0; s < STAGES - 1; ++s) { load_stage(s, s); CP_COMMIT(); }

    for (int t = 0; t < 48; ++t) {
        CP_WAIT2();                 // stage-t group complete (<=2 pending)
        __syncthreads();            // all threads' waits done + compute(t-1) done
        if (t + STAGES - 1 < 48) load_stage((t + STAGES - 1) & (STAGES - 1), t + STAGES - 1);
        CP_COMMIT();                // uniform commit (may be empty) keeps accounting

        const uint32_t stg = sb + (t & (STAGES - 1)) * STG_BYTES;
#pragma unroll
        for (int kg = 0; kg < 2; ++kg) {
            uint32_t bf[4][2];
#pragma unroll
            for (int nf = 0; nf < 4; ++nf) {
                const uint32_t ba = stg + B_OFF +
                    (uint32_t)(((wn * 4 + nf) * 2 + kg) * 256 + lane * 8);
                asm volatile("ld.shared.v2.b32 {%0,%1}, [%2];"
                             : "=r"(bf[nf][0]), "=r"(bf[nf][1]) : "r"(ba));
            }
#pragma unroll
            for (int mf = 0; mf < 4; ++mf) {
                uint32_t af[4];
                const uint32_t aa = stg +
                    (uint32_t)((((wm * 4 + mf) * 2 + kg) * 32 + lane) * 16);
                asm volatile("ld.shared.v4.b32 {%0,%1,%2,%3}, [%4];"
                             : "=r"(af[0]), "=r"(af[1]), "=r"(af[2]), "=r"(af[3])
                             : "r"(aa));
#pragma unroll
                for (int nf = 0; nf < 4; ++nf)
                    mma_f16(acc[mf][nf], af, bf[nf][0], bf[nf][1]);
            }
        }
    }

    // epilogue: BN + relu -> fp16 attr (half2 stores)
    const int g = lane >> 2, tq = lane & 3;
    __half* attrh = g_attrh + ((long)bI * OC + m0) * HW + hw0;
#pragma unroll
    for (int mf = 0; mf < 4; ++mf) {
        const int ml0 = wm * 64 + mf * 16 + g;
        const int ml1 = ml0 + 8;
        const float i0 = s_inv[ml0], z0 = s_bias[ml0];
        const float i1 = s_inv[ml1], z1 = s_bias[ml1];
#pragma unroll
        for (int nf = 0; nf < 4; ++nf) {
            const int n = wn * 32 + nf * 8 + 2 * tq;
            *(__half2*)(attrh + (long)ml0 * HW + n) =
                __floats2half2_rn(fmaxf(acc[mf][nf][0] * i0 + z0, 0.f),
                                  fmaxf(acc[mf][nf][1] * i0 + z0, 0.f));
            *(__half2*)(attrh + (long)ml1 * HW + n) =
                __floats2half2_rn(fmaxf(acc[mf][nf][2] * i1 + z1, 0.f),
                                  fmaxf(acc[mf][nf][3] * i1 + z1, 0.f));
        }
    }
}

// ---------------------------------------------------------------------------
// Kernel 3: ROI adaptive-avg-pool 5x5 over fp16 attr.
//   grid (160, 64): warp = (box, channel); lanes = aligned column pairs
//   (W=64 so ONE aligned 64-col chunk always covers the box).
// ---------------------------------------------------------------------------
__global__ __launch_bounds__(256) void pool_kernel(const float* __restrict__ boxes,
                                                   float* __restrict__ obj) {
    const int br = blockIdx.x;
    const int b  = br / 10;
    const float* bx = boxes + br * 4;

    int x1 = min(63, max(0, (int)floorf(bx[0] * 0.125f)));
    int y1 = min(63, max(0, (int)floorf(bx[1] * 0.125f)));
    int x2 = min(63, max(0, (int)ceilf (bx[2] * 0.125f)));
    int y2 = min(63, max(0, (int)ceilf (bx[3] * 0.125f)));
    if (x2 <= x1) x2 = min(x1 + 1, 64);
    if (y2 <= y1) y2 = min(y1 + 1, 64);
    const int Lx = x2 - x1, Ly = y2 - y1;

    int xs[5], xe[5], ys[5], ye[5];
    float invx[5], invy[5];
#pragma unroll
    for (int k = 0; k < 5; k++) {
        xs[k] = x1 + (k * Lx) / 5;
        xe[k] = x1 + ((k + 1) * Lx + 4) / 5;
        ys[k] = y1 + (k * Ly) / 5;
        ye[k] = y1 + ((k + 1) * Ly + 4) / 5;
        invx[k] = 1.f / (float)(xe[k] - xs[k]);
        invy[k] = 1.f / (float)(ye[k] - ys[k]);
    }

    const int warp = threadIdx.x >> 5, lane = threadIdx.x & 31;
    const int c = blockIdx.y * 8 + warp;
    const int cb = x1 & ~1;                       // aligned column base
    const int col0 = cb + 2 * lane, col1 = col0 + 1;
    const __half2* ch2 = (const __half2*)(g_attrh + ((long)b * OC + c) * HW) +
                         (cb >> 1) + lane;

    float2 cs[5];
#pragma unroll
    for (int p = 0; p < 5; p++) cs[p] = make_float2(0.f, 0.f);

#pragma unroll 4
    for (int h = y1; h < y2; h++) {
        const float2 v = __half22float2(ch2[h * 32]);
#pragma unroll
        for (int p = 0; p < 5; p++)
            if (h >= ys[p] && h < ye[p]) {
                cs[p].x += v.x * invy[p];
                cs[p].y += v.y * invy[p];
            }
    }

    float bins[25];
#pragma unroll
    for (int q = 0; q < 5; q++) {
        const float w0 = (col0 >= xs[q] && col0 < xe[q]) ? invx[q] : 0.f;
        const float w1 = (col1 >= xs[q] && col1 < xe[q]) ? invx[q] : 0.f;
#pragma unroll
        for (int p = 0; p < 5; p++)
            bins[p * 5 + q] = cs[p].x * w0 + cs[p].y * w1;
    }
#pragma unroll
    for (int t = 0; t < 25; t++) {
        float v = bins[t];
        v += __shfl_xor_sync(0xffffffffu, v, 16);
        v += __shfl_xor_sync(0xffffffffu, v, 8);
        v += __shfl_xor_sync(0xffffffffu, v, 4);
        v += __shfl_xor_sync(0xffffffffu, v, 2);
        v += __shfl_xor_sync(0xffffffffu, v, 1);
        bins[t] = v;
    }
    if (lane < 25) {
        float vout = 0.f;
#pragma unroll
        for (int t = 0; t < 25; t++)
            if (lane == t) vout = bins[t];
        obj[((long)br * OC + c) * 25 + lane] = vout;
    }
}

__global__ void copy_boxes_kernel(const float* __restrict__ boxes,
                                  float* __restrict__ out) {
    int i = blockIdx.x * blockDim.x + threadIdx.x;
    if (i < 640) out[i] = boxes[i];
}

// ---------------------------------------------------------------------------
extern "C" void kernel_launch(void* const* d_in, const int* in_sizes, int n_in,
                              void* d_out, int out_size) {
    const float* c3    = (const float*)d_in[0];
    const float* c4    = (const float*)d_in[1];
    const float* boxes = (const float*)d_in[2];
    const float* w     = (const float*)d_in[3];
    const float* bconv = (const float*)d_in[4];
    const float* gamma = (const float*)d_in[5];
    const float* beta  = (const float*)d_in[6];
    const float* mean  = (const float*)d_in[7];
    const float* var   = (const float*)d_in[8];

    float* out = (float*)d_out;
    float* obj = out;
    if (out_size >= 640 + 16 * 10 * 512 * 25) {
        copy_boxes_kernel<<<3, 256>>>(boxes, out);
        obj = out + 640;
    }

    cudaFuncSetAttribute(gemm_kernel, cudaFuncAttributeMaxDynamicSharedMemorySize,
                         GEMM_SMEM);

    wpack_kernel<<<(32 * NKT * 32 + 255) / 256, 256>>>(w);
    fuse_kernel<<<dim3(16, 24, 64), 256>>>(c3, c4);
    gemm_kernel<<<dim3(4, 512), 256, GEMM_SMEM>>>(bconv, gamma, beta, mean, var);
    pool_kernel<<<dim3(160, 64), 256>>>(boxes, obj);
}

// round 9
// speedup vs baseline: 4.5978x; 1.1141x over previous
#include <cuda_runtime.h>
#include <cuda_fp16.h>
#include <cstdint>

// ---------------------------------------------------------------------------
//   c3   : [16, 512, 64, 64] f32
//   c4   : [16,1024, 32, 32] f32
//   boxes: [16, 10, 4] f32
//   w    : [512, 1536] f32
//   out  : boxes (640 f32) ++ obj_blob [16,10,512,5,5]
// ---------------------------------------------------------------------------
#define OC   512
#define HW   4096
#define KD   1536
#define NKT  96                    // K / 16

// Scratch (device globals — allocation-free)
__device__ __align__(128) uint32_t g_wpack[OC * KD / 2];          // 1.5 MB
__device__ __align__(128) uint32_t g_bpack[16L * HW * KD / 2];    // 192 MB
__device__ __align__(128) __half   g_attrh[16L * OC * HW + 256];  // 64 MB fp16

// ---------------------------------------------------------------------------
// PTX helpers (baseline ISA only)
// ---------------------------------------------------------------------------
__device__ __forceinline__ uint32_t smem_u32(const void* p) {
    uint32_t a;
    asm("{ .reg .u64 t; cvta.to.shared.u64 t, %1; cvt.u32.u64 %0, t; }" : "=r"(a) : "l"(p));
    return a;
}
__device__ __forceinline__ void cp16(uint32_t dst, const void* src) {
    asm volatile("cp.async.cg.shared.global [%0], [%1], 16;" :: "r"(dst), "l"(src));
}
#define CP_COMMIT() asm volatile("cp.async.commit_group;" ::: "memory")
#define CP_WAIT2()  asm volatile("cp.async.wait_group 2;" ::: "memory")

__device__ __forceinline__ uint32_t pack_h2(float lo, float hi) {
    __half2 h = __floats2half2_rn(lo, hi);
    return *(uint32_t*)&h;
}
__device__ __forceinline__ void mma_f16(float* c, const uint32_t* a,
                                        uint32_t b0, uint32_t b1) {
    asm volatile(
        "mma.sync.aligned.m16n8k16.row.col.f32.f16.f16.f32 "
        "{%0,%1,%2,%3}, {%4,%5,%6,%7}, {%8,%9}, {%0,%1,%2,%3};"
        : "+f"(c[0]), "+f"(c[1]), "+f"(c[2]), "+f"(c[3])
        : "r"(a[0]), "r"(a[1]), "r"(a[2]), "r"(a[3]), "r"(b0), "r"(b1));
}

// ---------------------------------------------------------------------------
// Kernel 0: pack W -> fp16 A-fragment order (m16n8k16 layout)
// ---------------------------------------------------------------------------
__global__ void wpack_kernel(const float* __restrict__ w) {
    const int i = blockIdx.x * 256 + threadIdx.x;
    if (i >= 32 * NKT * 32) return;
    const int t = i >> 5, lane = i & 31;
    const int mt = t / NKT, kt = t % NKT;
    const int r = lane >> 2, c = lane & 3;
    const float* w0 = w + (long)(mt * 16 + r) * KD + kt * 16 + 2 * c;
    const float* w8 = w0 + 8 * KD;
    uint4 v;
    v.x = pack_h2(w0[0], w0[1]);
    v.y = pack_h2(w8[0], w8[1]);
    v.z = pack_h2(w0[8], w0[9]);
    v.w = pack_h2(w8[8], w8[9]);
    ((uint4*)g_wpack)[i] = v;
}

// ---------------------------------------------------------------------------
// Kernel 1: fused = concat(c3, bilinear2x(c4)) -> fp16 B-fragment-packed
//   grid (4 b, 24 ctile, 16 hquad), block 256.  Each block: 64 ch x 64 w x 4 h.
//   fp16 smem [4][64][66]: 33-word row stride -> conflict-free phase-2 reads.
// ---------------------------------------------------------------------------
__global__ __launch_bounds__(256) void fuse_kernel(const float* __restrict__ c3,
                                                   const float* __restrict__ c4,
                                                   int b0) {
    __shared__ __half s[4][64][66];
    const int b   = b0 + blockIdx.x;
    const int ct  = blockIdx.y;
    const int h0  = blockIdx.z * 4;
    const int tid = threadIdx.x;
    const int c0  = ct * 64;

    if (c0 < 512) {
        // pure c3 tile: float4-coalesced reads (1KB contiguous per channel row set)
#pragma unroll
        for (int hh = 0; hh < 4; ++hh) {
            for (int i = tid; i < 1024; i += 256) {
                const int w4 = i & 15, c = i >> 4;
                const float4 v = *(const float4*)(
                    c3 + (((long)(b * 512 + c0 + c)) << 12) + (h0 + hh) * 64 + w4 * 4);
                s[hh][w4 * 4 + 0][c] = __float2half(v.x);
                s[hh][w4 * 4 + 1][c] = __float2half(v.y);
                s[hh][w4 * 4 + 2][c] = __float2half(v.z);
                s[hh][w4 * 4 + 3][c] = __float2half(v.w);
            }
        }
    } else {
        const int cc0 = c0 - 512;
#pragma unroll
        for (int hh = 0; hh < 4; ++hh) {
            const int h = h0 + hh;
            const float syf = h * 0.5f - 0.25f;
            const float y0f = floorf(syf);
            const float fy  = syf - y0f;
            const int  iy0 = max(0, min(31, (int)y0f));
            const int  iy1 = max(0, min(31, (int)y0f + 1));
            for (int i = tid; i < 1024; i += 256) {
                const int w4 = i & 15, c = i >> 4;
                const float* src = c4 + ((long)(b * 1024 + cc0 + c)) * 1024;
                const float* r0 = src + iy0 * 32;
                const float* r1 = src + iy1 * 32;
#pragma unroll
                for (int j = 0; j < 4; ++j) {
                    const int w = w4 * 4 + j;
                    const float sxf = w * 0.5f - 0.25f;
                    const float x0f = floorf(sxf);
                    const float fx  = sxf - x0f;
                    const int ix0 = max(0, min(31, (int)x0f));
                    const int ix1 = max(0, min(31, (int)x0f + 1));
                    const float a  = r0[ix0] * (1.f - fx) + r0[ix1] * fx;
                    const float bb = r1[ix0] * (1.f - fx) + r1[ix1] * fx;
                    s[hh][w][c] = __float2half(a * (1.f - fy) + bb * fy);
                }
            }
        }
    }
    __syncthreads();

    // phase 2: pure uint32 shuffle -> fragment-packed gmem (same layout as R7)
    for (int i = tid; i < 1024; i += 256) {
        const int w   = i & 63;
        const int ktl = (i >> 6) & 3;
        const int hh  = i >> 8;
        const uint32_t* row = (const uint32_t*)&s[hh][w][0] + ktl * 8;
        const uint32_t u0 = row[0], u1 = row[1], u2 = row[2], u3 = row[3];
        const uint32_t u4 = row[4], u5 = row[5], u6 = row[6], u7 = row[7];
        uint4 lo = make_uint4(u0, u4, u1, u5);
        uint4 hi = make_uint4(u2, u6, u3, u7);
        const int  h    = h0 + hh;
        const long nt   = (long)b * 512 + ((h * 64 + w) >> 3);
        const long base = (nt * NKT + ct * 4 + ktl) * 64 + (w & 7) * 8;
        *(uint4*)(g_bpack + base)     = lo;
        *(uint4*)(g_bpack + base + 4) = hi;
    }
}

// ---------------------------------------------------------------------------
// Kernel 2: fp16 mma.sync GEMM, 4-stage single-sync cp.async pipeline
//   CTA 128x128, BK=32, 8 warps (2m x 4n), warp tile 64x32.
//   Per batch-group: grid (4, 128); b = b0 + (ny>>5).
// ---------------------------------------------------------------------------
#define STAGES    4
#define STG_BYTES 16384
#define B_OFF 8192
#define BN_OFF (STAGES * STG_BYTES)
#define GEMM_SMEM (BN_OFF + 1024)

__global__ __launch_bounds__(256, 2)
void gemm_kernel(const float* __restrict__ bconv, const float* __restrict__ gamma,
                 const float* __restrict__ beta,  const float* __restrict__ mean,
                 const float* __restrict__ var,   int b0) {
    extern __shared__ char smem[];
    const uint32_t sb = smem_u32(smem);
    const int tid  = threadIdx.x;
    const int wid  = tid >> 5, lane = tid & 31;
    const int wm   = wid >> 2;
    const int wn   = wid & 3;
    const int m0   = blockIdx.x * 128;
    const int ny   = blockIdx.y;
    const int bI   = b0 + (ny >> 5);
    const int hw0  = (ny & 31) * 128;

    float* s_inv  = (float*)(smem + BN_OFF);
    float* s_bias = s_inv + 128;
    if (tid < 128) {
        const int o = m0 + tid;
        const float iv = gamma[o] * rsqrtf(var[o] + 1e-5f);
        s_inv[tid]  = iv;
        s_bias[tid] = (bconv[o] - mean[o]) * iv + beta[o];
    }

    const uint4* Wp = (const uint4*)g_wpack;
    const uint4* Bp = (const uint4*)g_bpack;
    const int  mtb = blockIdx.x * 8;
    const long ntb = (long)bI * 512 + (ny & 31) * 16;

    long  aG[2], bG[2];
    uint32_t aS[2], bS[2];
#pragma unroll
    for (int j = 0; j < 2; ++j) {
        const int u = tid + j * 256;
        {
            const int mt_l = u >> 6, kt_l = (u >> 5) & 1, ln = u & 31;
            aG[j] = ((long)(mtb + mt_l) * NKT + kt_l) * 32 + ln;
            aS[j] = (uint32_t)u * 16;
        }
        {
            const int nt_l = u >> 5, kt_l = (u >> 4) & 1, p = u & 15;
            bG[j] = ((ntb + nt_l) * NKT + kt_l) * 16 + p;
            bS[j] = (uint32_t)(B_OFF + u * 16);
        }
    }

    auto load_stage = [&](int buf, int t) {
        const uint32_t stg = sb + buf * STG_BYTES;
#pragma unroll
        for (int j = 0; j < 2; ++j) {
            cp16(stg + aS[j], Wp + aG[j] + (long)t * 64);
            cp16(stg + bS[j], Bp + bG[j] + (long)t * 32);
        }
    };

    float acc[4][4][4];
#pragma unroll
    for (int i = 0; i < 4; i++)
#pragma unroll
        for (int j = 0; j < 4; j++)
#pragma unroll
            for (int k = 0; k < 4; k++) acc[i][j][k] = 0.f;

#pragma unroll
    for (int s = 0; s < STAGES - 1; ++s) { load_stage(s, s); CP_COMMIT(); }

    for (int t = 0; t < 48; ++t) {
        CP_WAIT2();
        __syncthreads();
        if (t + STAGES - 1 < 48) load_stage((t + STAGES - 1) & (STAGES - 1), t + STAGES - 1);
        CP_COMMIT();

        const uint32_t stg = sb + (t & (STAGES - 1)) * STG_BYTES;
#pragma unroll
        for (int kg = 0; kg < 2; ++kg) {
            uint32_t bf[4][2];
#pragma unroll
            for (int nf = 0; nf < 4; ++nf) {
                const uint32_t ba = stg + B_OFF +
                    (uint32_t)(((wn * 4 + nf) * 2 + kg) * 256 + lane * 8);
                asm volatile("ld.shared.v2.b32 {%0,%1}, [%2];"
                             : "=r"(bf[nf][0]), "=r"(bf[nf][1]) : "r"(ba));
            }
#pragma unroll
            for (int mf = 0; mf < 4; ++mf) {
                uint32_t af[4];
                const uint32_t aa = stg +
                    (uint32_t)((((wm * 4 + mf) * 2 + kg) * 32 + lane) * 16);
                asm volatile("ld.shared.v4.b32 {%0,%1,%2,%3}, [%4];"
                             : "=r"(af[0]), "=r"(af[1]), "=r"(af[2]), "=r"(af[3])
                             : "r"(aa));
#pragma unroll
                for (int nf = 0; nf < 4; ++nf)
                    mma_f16(acc[mf][nf], af, bf[nf][0], bf[nf][1]);
            }
        }
    }

    const int g = lane >> 2, tq = lane & 3;
    __half* attrh = g_attrh + ((long)bI * OC + m0) * HW + hw0;
#pragma unroll
    for (int mf = 0; mf < 4; ++mf) {
        const int ml0 = wm * 64 + mf * 16 + g;
        const int ml1 = ml0 + 8;
        const float i0 = s_inv[ml0], z0 = s_bias[ml0];
        const float i1 = s_inv[ml1], z1 = s_bias[ml1];
#pragma unroll
        for (int nf = 0; nf < 4; ++nf) {
            const int n = wn * 32 + nf * 8 + 2 * tq;
            *(__half2*)(attrh + (long)ml0 * HW + n) =
                __floats2half2_rn(fmaxf(acc[mf][nf][0] * i0 + z0, 0.f),
                                  fmaxf(acc[mf][nf][1] * i0 + z0, 0.f));
            *(__half2*)(attrh + (long)ml1 * HW + n) =
                __floats2half2_rn(fmaxf(acc[mf][nf][2] * i1 + z1, 0.f),
                                  fmaxf(acc[mf][nf][3] * i1 + z1, 0.f));
        }
    }
}

// ---------------------------------------------------------------------------
// Kernel 3: ROI adaptive-avg-pool 5x5 over fp16 attr.
//   Per batch-group: grid (40, 64); br = br0 + blockIdx.x.
// ---------------------------------------------------------------------------
__global__ __launch_bounds__(256) void pool_kernel(const float* __restrict__ boxes,
                                                   float* __restrict__ obj, int br0) {
    const int br = br0 + blockIdx.x;
    const int b  = br / 10;
    const float* bx = boxes + br * 4;

    int x1 = min(63, max(0, (int)floorf(bx[0] * 0.125f)));
    int y1 = min(63, max(0, (int)floorf(bx[1] * 0.125f)));
    int x2 = min(63, max(0, (int)ceilf (bx[2] * 0.125f)));
    int y2 = min(63, max(0, (int)ceilf (bx[3] * 0.125f)));
    if (x2 <= x1) x2 = min(x1 + 1, 64);
    if (y2 <= y1) y2 = min(y1 + 1, 64);
    const int Lx = x2 - x1, Ly = y2 - y1;

    int xs[5], xe[5], ys[5], ye[5];
    float invx[5], invy[5];
#pragma unroll
    for (int k = 0; k < 5; k++) {
        xs[k] = x1 + (k * Lx) / 5;
        xe[k] = x1 + ((k + 1) * Lx + 4) / 5;
        ys[k] = y1 + (k * Ly) / 5;
        ye[k] = y1 + ((k + 1) * Ly + 4) / 5;
        invx[k] = 1.f / (float)(xe[k] - xs[k]);
        invy[k] = 1.f / (float)(ye[k] - ys[k]);
    }

    const int warp = threadIdx.x >> 5, lane = threadIdx.x & 31;
    const int c = blockIdx.y * 8 + warp;
    const int cb = x1 & ~1;
    const int col0 = cb + 2 * lane, col1 = col0 + 1;
    const __half2* ch2 = (const __half2*)(g_attrh + ((long)b * OC + c) * HW) +
                         (cb >> 1) + lane;

    float2 cs[5];
#pragma unroll
    for (int p = 0; p < 5; p++) cs[p] = make_float2(0.f, 0.f);

#pragma unroll 4
    for (int h = y1; h < y2; h++) {
        const float2 v = __half22float2(ch2[h * 32]);
#pragma unroll
        for (int p = 0; p < 5; p++)
            if (h >= ys[p] && h < ye[p]) {
                cs[p].x += v.x * invy[p];
                cs[p].y += v.y * invy[p];
            }
    }

    float bins[25];
#pragma unroll
    for (int q = 0; q < 5; q++) {
        const float w0 = (col0 >= xs[q] && col0 < xe[q]) ? invx[q] : 0.f;
        const float w1 = (col1 >= xs[q] && col1 < xe[q]) ? invx[q] : 0.f;
#pragma unroll
        for (int p = 0; p < 5; p++)
            bins[p * 5 + q] = cs[p].x * w0 + cs[p].y * w1;
    }
#pragma unroll
    for (int t = 0; t < 25; t++) {
        float v = bins[t];
        v += __shfl_xor_sync(0xffffffffu, v, 16);
        v += __shfl_xor_sync(0xffffffffu, v, 8);
        v += __shfl_xor_sync(0xffffffffu, v, 4);
        v += __shfl_xor_sync(0xffffffffu, v, 2);
        v += __shfl_xor_sync(0xffffffffu, v, 1);
        bins[t] = v;
    }
    if (lane < 25) {
        float vout = 0.f;
#pragma unroll
        for (int t = 0; t < 25; t++)
            if (lane == t) vout = bins[t];
        obj[((long)br * OC + c) * 25 + lane] = vout;
    }
}

__global__ void copy_boxes_kernel(const float* __restrict__ boxes,
                                  float* __restrict__ out) {
    int i = blockIdx.x * blockDim.x + threadIdx.x;
    if (i < 640) out[i] = boxes[i];
}

// ---------------------------------------------------------------------------
// Launch: 2-stream batch-group pipeline (fork/join off default stream so the
// whole thing is graph-capturable; streams/events created once on the first,
// pre-capture correctness call — no allocation, no sync inside this function).
// ---------------------------------------------------------------------------
#define NGRP 4

extern "C" void kernel_launch(void* const* d_in, const int* in_sizes, int n_in,
                              void* d_out, int out_size) {
    const float* c3    = (const float*)d_in[0];
    const float* c4    = (const float*)d_in[1];
    const float* boxes = (const float*)d_in[2];
    const float* w     = (const float*)d_in[3];
    const float* bconv = (const float*)d_in[4];
    const float* gamma = (const float*)d_in[5];
    const float* beta  = (const float*)d_in[6];
    const float* mean  = (const float*)d_in[7];
    const float* var   = (const float*)d_in[8];

    static cudaStream_t s1 = nullptr;
    static cudaEvent_t eFork, eJoin, eF[NGRP], eG[NGRP];
    if (s1 == nullptr) {
        cudaStreamCreateWithFlags(&s1, cudaStreamNonBlocking);
        cudaEventCreateWithFlags(&eFork, cudaEventDisableTiming);
        cudaEventCreateWithFlags(&eJoin, cudaEventDisableTiming);
        for (int g = 0; g < NGRP; ++g) {
            cudaEventCreateWithFlags(&eF[g], cudaEventDisableTiming);
            cudaEventCreateWithFlags(&eG[g], cudaEventDisableTiming);
        }
        cudaFuncSetAttribute(gemm_kernel, cudaFuncAttributeMaxDynamicSharedMemorySize,
                             GEMM_SMEM);
    }

    float* out = (float*)d_out;
    float* obj = out;
    const bool with_boxes = (out_size >= 640 + 16 * 10 * 512 * 25);
    if (with_boxes) obj = out + 640;

    // default stream: weight pack (needed by all gemms)
    wpack_kernel<<<(32 * NKT * 32 + 255) / 256, 256>>>(w);

    // fork side stream
    cudaEventRecord(eFork, 0);
    cudaStreamWaitEvent(s1, eFork, 0);

    if (with_boxes) copy_boxes_kernel<<<3, 256, 0, s1>>>(boxes, out);

    // s1: fuse groups (producers)
    for (int g = 0; g < NGRP; ++g) {
        fuse_kernel<<<dim3(4, 24, 16), 256, 0, s1>>>(c3, c4, g * 4);
        cudaEventRecord(eF[g], s1);
    }
    // default stream: gemm groups, each gated on its fuse group
    for (int g = 0; g < NGRP; ++g) {
        cudaStreamWaitEvent(0, eF[g], 0);
        gemm_kernel<<<dim3(4, 128), 256, GEMM_SMEM>>>(bconv, gamma, beta, mean, var,
                                                      g * 4);
        cudaEventRecord(eG[g], 0);
    }
    // s1: pool groups, each gated on its gemm group
    for (int g = 0; g < NGRP; ++g) {
        cudaStreamWaitEvent(s1, eG[g], 0);
        pool_kernel<<<dim3(40, 64), 256, 0, s1>>>(boxes, obj, g * 40);
    }

    // join
    cudaEventRecord(eJoin, s1);
    cudaStreamWaitEvent(0, eJoin, 0);
}

// round 11
// speedup vs baseline: 5.1171x; 1.1129x over previous
#include <cuda_runtime.h>
#include <cuda_fp16.h>
#include <cstdint>

// ---------------------------------------------------------------------------
//   c3   : [16, 512, 64, 64] f32
//   c4   : [16,1024, 32, 32] f32
//   boxes: [16, 10, 4] f32
//   w    : [512, 1536] f32
//   out  : boxes (640 f32) ++ obj_blob [16,10,512,5,5]
// ---------------------------------------------------------------------------
#define OC   512
#define HW   4096
#define KD   1536
#define NKT  96                    // K / 16

// Scratch (device globals — allocation-free)
__device__ __align__(128) uint32_t g_wpack[OC * KD / 2];          // 1.5 MB
__device__ __align__(128) uint32_t g_bpack[16L * HW * KD / 2];    // 192 MB
__device__ __align__(128) __half   g_attrh[16L * OC * HW + 256];  // 64 MB fp16

// ---------------------------------------------------------------------------
// PTX helpers (baseline ISA only)
// ---------------------------------------------------------------------------
__device__ __forceinline__ uint32_t smem_u32(const void* p) {
    uint32_t a;
    asm("{ .reg .u64 t; cvta.to.shared.u64 t, %1; cvt.u32.u64 %0, t; }" : "=r"(a) : "l"(p));
    return a;
}
__device__ __forceinline__ void cp16(uint32_t dst, const void* src) {
    asm volatile("cp.async.cg.shared.global [%0], [%1], 16;" :: "r"(dst), "l"(src));
}
#define CP_COMMIT() asm volatile("cp.async.commit_group;" ::: "memory")
#define CP_WAIT2()  asm volatile("cp.async.wait_group 2;" ::: "memory")

__device__ __forceinline__ uint32_t pack_h2(float lo, float hi) {
    __half2 h = __floats2half2_rn(lo, hi);
    return *(uint32_t*)&h;
}
__device__ __forceinline__ void mma_f16(float* c, const uint32_t* a,
                                        uint32_t b0, uint32_t b1) {
    asm volatile(
        "mma.sync.aligned.m16n8k16.row.col.f32.f16.f16.f32 "
        "{%0,%1,%2,%3}, {%4,%5,%6,%7}, {%8,%9}, {%0,%1,%2,%3};"
        : "+f"(c[0]), "+f"(c[1]), "+f"(c[2]), "+f"(c[3])
        : "r"(a[0]), "r"(a[1]), "r"(a[2]), "r"(a[3]), "r"(b0), "r"(b1));
}

// ---------------------------------------------------------------------------
// Kernel 0: pack W -> fp16 A-fragment order (m16n8k16 layout)
// ---------------------------------------------------------------------------
__global__ void wpack_kernel(const float* __restrict__ w) {
    const int i = blockIdx.x * 256 + threadIdx.x;
    if (i >= 32 * NKT * 32) return;
    const int t = i >> 5, lane = i & 31;
    const int mt = t / NKT, kt = t % NKT;
    const int r = lane >> 2, c = lane & 3;
    const float* w0 = w + (long)(mt * 16 + r) * KD + kt * 16 + 2 * c;
    const float* w8 = w0 + 8 * KD;
    uint4 v;
    v.x = pack_h2(w0[0], w0[1]);
    v.y = pack_h2(w8[0], w8[1]);
    v.z = pack_h2(w0[8], w0[9]);
    v.w = pack_h2(w8[8], w8[9]);
    ((uint4*)g_wpack)[i] = v;
}

// ---------------------------------------------------------------------------
// Kernel 1: fused = concat(c3, bilinear2x(c4)) -> fp16 B-fragment-packed
//   grid (16 b, 24 ctile, 16 hquad), block 256.  Block: 64 ch x 64 w x 4 h.
//   smem packs 2 channels per uint32 -> 32-bit STS, half the converts/stores.
// ---------------------------------------------------------------------------
__global__ __launch_bounds__(256) void fuse_kernel(const float* __restrict__ c3,
                                                   const float* __restrict__ c4) {
    __shared__ uint32_t s[4][64][33];       // [h][w][c2]: channels 2c2, 2c2+1
    const int b   = blockIdx.x;
    const int ct  = blockIdx.y;
    const int h0  = blockIdx.z * 4;
    const int tid = threadIdx.x;
    const int c0  = ct * 64;

    if (c0 < 512) {
        // pure c3 tile: two float4-coalesced channel rows per thread-iter
#pragma unroll
        for (int hh = 0; hh < 4; ++hh) {
#pragma unroll
            for (int it = 0; it < 2; ++it) {
                const int i  = tid + it * 256;          // 0..511
                const int w4 = i & 15, c2 = i >> 4;     // c2: 0..31
                const long base = (((long)(b * 512 + c0 + 2 * c2)) << 12) +
                                  (h0 + hh) * 64 + w4 * 4;
                const float4 f0 = *(const float4*)(c3 + base);
                const float4 f1 = *(const float4*)(c3 + base + HW);
                s[hh][w4 * 4 + 0][c2] = pack_h2(f0.x, f1.x);
                s[hh][w4 * 4 + 1][c2] = pack_h2(f0.y, f1.y);
                s[hh][w4 * 4 + 2][c2] = pack_h2(f0.z, f1.z);
                s[hh][w4 * 4 + 3][c2] = pack_h2(f0.w, f1.w);
            }
        }
    } else {
        const int cc0 = c0 - 512;
#pragma unroll
        for (int hh = 0; hh < 4; ++hh) {
            const int h = h0 + hh;
            const float syf = h * 0.5f - 0.25f;
            const float y0f = floorf(syf);
            const float fy  = syf - y0f;
            const int  iy0 = max(0, min(31, (int)y0f));
            const int  iy1 = max(0, min(31, (int)y0f + 1));
#pragma unroll
            for (int it = 0; it < 2; ++it) {
                const int i  = tid + it * 256;
                const int w4 = i & 15, c2 = i >> 4;
                const float* srcA = c4 + ((long)(b * 1024 + cc0 + 2 * c2)) * 1024;
                const float* srcB = srcA + 1024;
                const float* a0 = srcA + iy0 * 32;
                const float* a1 = srcA + iy1 * 32;
                const float* b0p = srcB + iy0 * 32;
                const float* b1p = srcB + iy1 * 32;
#pragma unroll
                for (int j = 0; j < 4; ++j) {
                    const int w = w4 * 4 + j;
                    const float sxf = w * 0.5f - 0.25f;
                    const float x0f = floorf(sxf);
                    const float fx  = sxf - x0f;
                    const int ix0 = max(0, min(31, (int)x0f));
                    const int ix1 = max(0, min(31, (int)x0f + 1));
                    const float wa = (1.f - fx) * (1.f - fy), wb = fx * (1.f - fy);
                    const float wc = (1.f - fx) * fy,          wd = fx * fy;
                    const float vA = a0[ix0] * wa + a0[ix1] * wb +
                                     a1[ix0] * wc + a1[ix1] * wd;
                    const float vB = b0p[ix0] * wa + b0p[ix1] * wb +
                                     b1p[ix0] * wc + b1p[ix1] * wd;
                    s[hh][w][c2] = pack_h2(vA, vB);
                }
            }
        }
    }
    __syncthreads();

    // phase 2: uint32 shuffle -> fragment-packed gmem (layout unchanged)
    for (int i = tid; i < 1024; i += 256) {
        const int w   = i & 63;
        const int ktl = (i >> 6) & 3;
        const int hh  = i >> 8;
        const uint32_t* row = &s[hh][w][0] + ktl * 8;
        uint4 lo = make_uint4(row[0], row[4], row[1], row[5]);
        uint4 hi = make_uint4(row[2], row[6], row[3], row[7]);
        const int  h    = h0 + hh;
        const long nt   = (long)b * 512 + ((h * 64 + w) >> 3);
        const long base = (nt * NKT + ct * 4 + ktl) * 64 + (w & 7) * 8;
        *(uint4*)(g_bpack + base)     = lo;
        *(uint4*)(g_bpack + base + 4) = hi;
    }
}

// ---------------------------------------------------------------------------
// Kernel 2: fp16 mma.sync GEMM, 4-stage single-sync cp.async pipeline
//   CTA 128x128, BK=32, 8 warps (2m x 4n), warp tile 64x32.  grid (4, 512).
// ---------------------------------------------------------------------------
#define STAGES    4
#define STG_BYTES 16384
#define B_OFF 8192
#define BN_OFF (STAGES * STG_BYTES)
#define GEMM_SMEM (BN_OFF + 1024)

__global__ __launch_bounds__(256, 2)
void gemm_kernel(const float* __restrict__ bconv, const float* __restrict__ gamma,
                 const float* __restrict__ beta,  const float* __restrict__ mean,
                 const float* __restrict__ var) {
    extern __shared__ char smem[];
    const uint32_t sb = smem_u32(smem);
    const int tid  = threadIdx.x;
    const int wid  = tid >> 5, lane = tid & 31;
    const int wm   = wid >> 2;
    const int wn   = wid & 3;
    const int m0   = blockIdx.x * 128;
    const int ny   = blockIdx.y;
    const int bI   = ny >> 5;
    const int hw0  = (ny & 31) * 128;

    float* s_inv  = (float*)(smem + BN_OFF);
    float* s_bias = s_inv + 128;
    if (tid < 128) {
        const int o = m0 + tid;
        const float iv = gamma[o] * rsqrtf(var[o] + 1e-5f);
        s_inv[tid]  = iv;
        s_bias[tid] = (bconv[o] - mean[o]) * iv + beta[o];
    }

    const uint4* Wp = (const uint4*)g_wpack;
    const uint4* Bp = (const uint4*)g_bpack;
    const int  mtb = blockIdx.x * 8;
    const long ntb = (long)bI * 512 + (ny & 31) * 16;

    long  aG[2], bG[2];
    uint32_t aS[2], bS[2];
#pragma unroll
    for (int j = 0; j < 2; ++j) {
        const int u = tid + j * 256;
        {
            const int mt_l = u >> 6, kt_l = (u >> 5) & 1, ln = u & 31;
            aG[j] = ((long)(mtb + mt_l) * NKT + kt_l) * 32 + ln;
            aS[j] = (uint32_t)u * 16;
        }
        {
            const int nt_l = u >> 5, kt_l = (u >> 4) & 1, p = u & 15;
            bG[j] = ((ntb + nt_l) * NKT + kt_l) * 16 + p;
            bS[j] = (uint32_t)(B_OFF + u * 16);
        }
    }

    auto load_stage = [&](int buf, int t) {
        const uint32_t stg = sb + buf * STG_BYTES;
#pragma unroll
        for (int j = 0; j < 2; ++j) {
            cp16(stg + aS[j], Wp + aG[j] + (long)t * 64);
            cp16(stg + bS[j], Bp + bG[j] + (long)t * 32);
        }
    };

    float acc[4][4][4];
#pragma unroll
    for (int i = 0; i < 4; i++)
#pragma unroll
        for (int j = 0; j < 4; j++)
#pragma unroll
            for (int k = 0; k < 4; k++) acc[i][j][k] = 0.f;

#pragma unroll
    for (int s = 0; s < STAGES - 1; ++s) { load_stage(s, s); CP_COMMIT(); }

    for (int t = 0; t < 48; ++t) {
        CP_WAIT2();
        __syncthreads();
        if (t + STAGES - 1 < 48) load_stage((t + STAGES - 1) & (STAGES - 1), t + STAGES - 1);
        CP_COMMIT();

        const uint32_t stg = sb + (t & (STAGES - 1)) * STG_BYTES;
#pragma unroll
        for (int kg = 0; kg < 2; ++kg) {
            uint32_t bf[4][2];
#pragma unroll
            for (int nf = 0; nf < 4; ++nf) {
                const uint32_t ba = stg + B_OFF +
                    (uint32_t)(((wn * 4 + nf) * 2 + kg) * 256 + lane * 8);
                asm volatile("ld.shared.v2.b32 {%0,%1}, [%2];"
                             : "=r"(bf[nf][0]), "=r"(bf[nf][1]) : "r"(ba));
            }
#pragma unroll
            for (int mf = 0; mf < 4; ++mf) {
                uint32_t af[4];
                const uint32_t aa = stg +
                    (uint32_t)((((wm * 4 + mf) * 2 + kg) * 32 + lane) * 16);
                asm volatile("ld.shared.v4.b32 {%0,%1,%2,%3}, [%4];"
                             : "=r"(af[0]), "=r"(af[1]), "=r"(af[2]), "=r"(af[3])
                             : "r"(aa));
#pragma unroll
                for (int nf = 0; nf < 4; ++nf)
                    mma_f16(acc[mf][nf], af, bf[nf][0], bf[nf][1]);
            }
        }
    }

    const int g = lane >> 2, tq = lane & 3;
    __half* attrh = g_attrh + ((long)bI * OC + m0) * HW + hw0;
#pragma unroll
    for (int mf = 0; mf < 4; ++mf) {
        const int ml0 = wm * 64 + mf * 16 + g;
        const int ml1 = ml0 + 8;
        const float i0 = s_inv[ml0], z0 = s_bias[ml0];
        const float i1 = s_inv[ml1], z1 = s_bias[ml1];
#pragma unroll
        for (int nf = 0; nf < 4; ++nf) {
            const int n = wn * 32 + nf * 8 + 2 * tq;
            *(__half2*)(attrh + (long)ml0 * HW + n) =
                __floats2half2_rn(fmaxf(acc[mf][nf][0] * i0 + z0, 0.f),
                                  fmaxf(acc[mf][nf][1] * i0 + z0, 0.f));
            *(__half2*)(attrh + (long)ml1 * HW + n) =
                __floats2half2_rn(fmaxf(acc[mf][nf][2] * i1 + z1, 0.f),
                                  fmaxf(acc[mf][nf][3] * i1 + z1, 0.f));
        }
    }
}

// ---------------------------------------------------------------------------
// Kernel 3: ROI adaptive-avg-pool 5x5 over fp16 attr.  grid (160, 64).
//   Lanes whose column pair misses the box skip all loads (saves ~3x traffic).
// ---------------------------------------------------------------------------
__global__ __launch_bounds__(256) void pool_kernel(const float* __restrict__ boxes,
                                                   float* __restrict__ obj) {
    const int br = blockIdx.x;
    const int b  = br / 10;
    const float* bx = boxes + br * 4;

    int x1 = min(63, max(0, (int)floorf(bx[0] * 0.125f)));
    int y1 = min(63, max(0, (int)floorf(bx[1] * 0.125f)));
    int x2 = min(63, max(0, (int)ceilf (bx[2] * 0.125f)));
    int y2 = min(63, max(0, (int)ceilf (bx[3] * 0.125f)));
    if (x2 <= x1) x2 = min(x1 + 1, 64);
    if (y2 <= y1) y2 = min(y1 + 1, 64);
    const int Lx = x2 - x1, Ly = y2 - y1;

    int xs[5], xe[5], ys[5], ye[5];
    float invx[5], invy[5];
#pragma unroll
    for (int k = 0; k < 5; k++) {
        xs[k] = x1 + (k * Lx) / 5;
        xe[k] = x1 + ((k + 1) * Lx + 4) / 5;
        ys[k] = y1 + (k * Ly) / 5;
        ye[k] = y1 + ((k + 1) * Ly + 4) / 5;
        invx[k] = 1.f / (float)(xe[k] - xs[k]);
        invy[k] = 1.f / (float)(ye[k] - ys[k]);
    }

    const int warp = threadIdx.x >> 5, lane = threadIdx.x & 31;
    const int c = blockIdx.y * 8 + warp;
    const int cb = x1 & ~1;
    const int col0 = cb + 2 * lane, col1 = col0 + 1;
    const bool inx = (col1 >= x1) && (col0 < x2);
    const __half2* ch2 = (const __half2*)(g_attrh + ((long)b * OC + c) * HW) +
                         (cb >> 1) + lane;

    float2 cs[5];
#pragma unroll
    for (int p = 0; p < 5; p++) cs[p] = make_float2(0.f, 0.f);

    if (inx) {
#pragma unroll 4
        for (int h = y1; h < y2; h++) {
            const float2 v = __half22float2(ch2[h * 32]);
#pragma unroll
            for (int p = 0; p < 5; p++)
                if (h >= ys[p] && h < ye[p]) {
                    cs[p].x += v.x * invy[p];
                    cs[p].y += v.y * invy[p];
                }
        }
    }

    float bins[25];
#pragma unroll
    for (int q = 0; q < 5; q++) {
        const float w0 = (col0 >= xs[q] && col0 < xe[q]) ? invx[q] : 0.f;
        const float w1 = (col1 >= xs[q] && col1 < xe[q]) ? invx[q] : 0.f;
#pragma unroll
        for (int p = 0; p < 5; p++)
            bins[p * 5 + q] = cs[p].x * w0 + cs[p].y * w1;
    }
#pragma unroll
    for (int t = 0; t < 25; t++) {
        float v = bins[t];
        v += __shfl_xor_sync(0xffffffffu, v, 16);
        v += __shfl_xor_sync(0xffffffffu, v, 8);
        v += __shfl_xor_sync(0xffffffffu, v, 4);
        v += __shfl_xor_sync(0xffffffffu, v, 2);
        v += __shfl_xor_sync(0xffffffffu, v, 1);
        bins[t] = v;
    }
    if (lane < 25) {
        float vout = 0.f;
#pragma unroll
        for (int t = 0; t < 25; t++)
            if (lane == t) vout = bins[t];
        obj[((long)br * OC + c) * 25 + lane] = vout;
    }
}

__global__ void copy_boxes_kernel(const float* __restrict__ boxes,
                                  float* __restrict__ out) {
    int i = blockIdx.x * blockDim.x + threadIdx.x;
    if (i < 640) out[i] = boxes[i];
}

// ---------------------------------------------------------------------------
extern "C" void kernel_launch(void* const* d_in, const int* in_sizes, int n_in,
                              void* d_out, int out_size) {
    const float* c3    = (const float*)d_in[0];
    const float* c4    = (const float*)d_in[1];
    const float* boxes = (const float*)d_in[2];
    const float* w     = (const float*)d_in[3];
    const float* bconv = (const float*)d_in[4];
    const float* gamma = (const float*)d_in[5];
    const float* beta  = (const float*)d_in[6];
    const float* mean  = (const float*)d_in[7];
    const float* var   = (const float*)d_in[8];

    float* out = (float*)d_out;
    float* obj = out;
    if (out_size >= 640 + 16 * 10 * 512 * 25) {
        copy_boxes_kernel<<<3, 256>>>(boxes, out);
        obj = out + 640;
    }

    cudaFuncSetAttribute(gemm_kernel, cudaFuncAttributeMaxDynamicSharedMemorySize,
                         GEMM_SMEM);

    wpack_kernel<<<(32 * NKT * 32 + 255) / 256, 256>>>(w);
    fuse_kernel<<<dim3(16, 24, 16), 256>>>(c3, c4);
    gemm_kernel<<<dim3(4, 512), 256, GEMM_SMEM>>>(bconv, gamma, beta, mean, var);
    pool_kernel<<<dim3(160, 64), 256>>>(boxes, obj);
}